// round 12
// baseline (speedup 1.0000x reference)
#include <cuda_runtime.h>
#include <cuda_fp16.h>
#include <math.h>
#include <cstdint>

#define NH   8
#define HD   24
#define CDIM 192
#define HW   65536   // 256*256
#define NB   4
#define KDIM 192
#define MQ   640     // qkv rows padded to 5*128 (576 valid)
#define MP   256
#define NWIN 1024    // 32x32 windows

#define BPADH  136
#define APM    12288
// gemm8 smem (bytes): A frags @0 : 49152 ; B fp16 bufs @49152 : 2 x 52224
#define SB_TILE 49152
#define BBYTES  52224
#define SMEM_G  153600
#define TILES_PER_CTA 8

// ---------------- device scratch (fp16 window-native intermediates) ----------------
__device__ __half   g_qkvh[(size_t)NB * NWIN * 576 * 64];   // (B, win, ch, tok)
__device__ __half   g_atth[(size_t)NB * NWIN * CDIM * 64];  // (B, win, ch, tok)
__device__ float    g_bias[NH * 64 * 64];
__device__ unsigned g_wqf[5 * APM];
__device__ unsigned g_wpf[2 * APM];
__device__ float    g_bq[MQ];
__device__ float    g_bp[MP];

// ---------------- helpers ----------------
__device__ __forceinline__ uint32_t smem_u32(const void* p) {
    uint32_t a;
    asm("{ .reg .u64 t; cvta.to.shared.u64 t, %1; cvt.u32.u64 %0, t; }" : "=r"(a) : "l"(p));
    return a;
}
__device__ __forceinline__ void cpa16(uint32_t dst, const void* src) {
    asm volatile("cp.async.cg.shared.global [%0], [%1], 16;" :: "r"(dst), "l"(src));
}
__device__ __forceinline__ void lds128(uint32_t* r, uint32_t a) {
    asm volatile("ld.shared.v4.b32 {%0,%1,%2,%3}, [%4];"
                 : "=r"(r[0]), "=r"(r[1]), "=r"(r[2]), "=r"(r[3]) : "r"(a));
}
__device__ __forceinline__ void ldmx4(uint32_t* r, uint32_t a) {
    asm volatile("ldmatrix.sync.aligned.m8n8.x4.shared.b16 {%0,%1,%2,%3}, [%4];"
                 : "=r"(r[0]), "=r"(r[1]), "=r"(r[2]), "=r"(r[3]) : "r"(a));
}
__device__ __forceinline__ void ldmx4t(uint32_t* r, uint32_t a) {
    asm volatile("ldmatrix.sync.aligned.m8n8.x4.trans.shared.b16 {%0,%1,%2,%3}, [%4];"
                 : "=r"(r[0]), "=r"(r[1]), "=r"(r[2]), "=r"(r[3]) : "r"(a));
}
__device__ __forceinline__ void ldmx2(uint32_t* r, uint32_t a) {
    asm volatile("ldmatrix.sync.aligned.m8n8.x2.shared.b16 {%0,%1}, [%2];"
                 : "=r"(r[0]), "=r"(r[1]) : "r"(a));
}
__device__ __forceinline__ void mma_f16(float* c, const uint32_t* a, const uint32_t* b) {
    asm volatile("mma.sync.aligned.m16n8k16.row.col.f32.f16.f16.f32 "
                 "{%0,%1,%2,%3}, {%4,%5,%6,%7}, {%8,%9}, {%0,%1,%2,%3};"
                 : "+f"(c[0]), "+f"(c[1]), "+f"(c[2]), "+f"(c[3])
                 : "r"(a[0]), "r"(a[1]), "r"(a[2]), "r"(a[3]), "r"(b[0]), "r"(b[1]));
}
__device__ __forceinline__ uint32_t pack_h2(float lo, float hi) {
    __half2 h = __floats2half2_rn(lo, hi);
    return *(uint32_t*)&h;
}

// one k16 step of the 128x128 tile (warp tile 32x64)
__device__ __forceinline__ void gemm_kk(uint32_t sb, uint32_t Bb, int wm, int lane,
                                        float acc[2][8][4], int kk)
{
    uint32_t a[2][4];
    const uint32_t Ab = sb + (kk >> 1) * 8192;
    lds128(a[0], Ab + (((kk & 1) * 8 + wm * 2 + 0) * 32 + lane) * 16);
    lds128(a[1], Ab + (((kk & 1) * 8 + wm * 2 + 1) * 32 + lane) * 16);
    uint32_t bm[4][4];
    #pragma unroll
    for (int nfp = 0; nfp < 4; nfp++)
        ldmx4t(bm[nfp], Bb + (uint32_t)((kk * 16 * BPADH + nfp * 16) * 2));
    #pragma unroll
    for (int mf = 0; mf < 2; mf++)
        #pragma unroll
        for (int nf = 0; nf < 8; nf++)
            mma_f16(acc[mf][nf], a[mf], &bm[nf >> 1][(nf & 1) * 2]);
}

// ---------------- kernel 1: CPB bias table ----------------
__global__ void bias_kernel(const float* __restrict__ w1, const float* __restrict__ b1,
                            const float* __restrict__ w2)
{
    __shared__ float table[225][NH];
    int tid = threadIdx.x;

    if (tid < 225) {
        int a = tid / 15, b = tid % 15;
        const float inv_l8 = 1.0f / log2f(8.0f);
        float ca = (float)(a - 7) / 7.0f * 8.0f;
        float cb = (float)(b - 7) / 7.0f * 8.0f;
        float r0 = (ca == 0.f) ? 0.f : copysignf(log2f(fabsf(ca) + 1.0f) * inv_l8, ca);
        float r1 = (cb == 0.f) ? 0.f : copysignf(log2f(fabsf(cb) + 1.0f) * inv_l8, cb);
        float acc[NH];
        #pragma unroll
        for (int h = 0; h < NH; h++) acc[h] = 0.f;
        for (int j = 0; j < 512; j++) {
            float hv = fmaf(r0, w1[j], fmaf(r1, w1[512 + j], b1[j]));
            hv = fmaxf(hv, 0.f);
            #pragma unroll
            for (int h = 0; h < NH; h++) acc[h] = fmaf(hv, w2[j * NH + h], acc[h]);
        }
        #pragma unroll
        for (int h = 0; h < NH; h++) table[tid][h] = acc[h];
    }
    __syncthreads();

    for (int idx = tid; idx < NH * 64 * 64; idx += blockDim.x) {
        int h  = idx / (64 * 64);
        int nm = idx % (64 * 64);
        int n = nm / 64, m = nm % 64;
        int di = (n >> 3) - (m >> 3) + 7;
        int dj = (n & 7) - (m & 7) + 7;
        float t = table[di * 15 + dj][h];
        g_bias[idx] = 16.f / (1.f + expf(-t));
    }
}

// ---------------- kernel 1b: pack weights into fp16 m16n8k16 fragment layout ----------------
__global__ void prep_kernel(const float* __restrict__ qkv_w, const float* __restrict__ qb,
                            const float* __restrict__ vb,
                            const float* __restrict__ proj_w, const float* __restrict__ pb)
{
    int i = blockIdx.x * blockDim.x + threadIdx.x;
    int stride = gridDim.x * blockDim.x;

    for (int idx = i; idx < 5 * APM; idx += stride) {
        int mt  = idx / APM;
        int r   = idx % APM;
        int kst = r / 2048;
        int r2  = r % 2048;
        int slot = r2 & 3, lane = (r2 >> 2) & 31, mf = (r2 >> 7) & 7, ks = (r2 >> 10) & 1;
        int m = mt * 128 + mf * 16 + (lane >> 2) + (slot & 1) * 8;
        int k = kst * 32 + ks * 16 + (lane & 3) * 2 + ((slot >> 1) & 1) * 8;
        float v0 = (m < 576) ? qkv_w[m * KDIM + k]     : 0.f;
        float v1 = (m < 576) ? qkv_w[m * KDIM + k + 1] : 0.f;
        g_wqf[idx] = pack_h2(v0, v1);
    }
    for (int idx = i; idx < 2 * APM; idx += stride) {
        int mt  = idx / APM;
        int r   = idx % APM;
        int kst = r / 2048;
        int r2  = r % 2048;
        int slot = r2 & 3, lane = (r2 >> 2) & 31, mf = (r2 >> 7) & 7, ks = (r2 >> 10) & 1;
        int m = mt * 128 + mf * 16 + (lane >> 2) + (slot & 1) * 8;
        int k = kst * 32 + ks * 16 + (lane & 3) * 2 + ((slot >> 1) & 1) * 8;
        float v0 = (m < 192) ? proj_w[m * KDIM + k]     : 0.f;
        float v1 = (m < 192) ? proj_w[m * KDIM + k + 1] : 0.f;
        g_wpf[idx] = pack_h2(v0, v1);
    }
    if (i < MQ) {
        float v = 0.f;
        if (i < 192)                  v = qb[i];
        else if (i >= 384 && i < 576) v = vb[i - 384];
        g_bq[i] = v;
    }
    if (i < MP) g_bp[i] = (i < 192) ? pb[i] : 0.f;
}

// ---------------- kernel 2/4: persistent-tile fp16 GEMM, A resident, B double-buffered ----------------
// 256 threads (8 warps: wm 0..3, wn 0..1), warp tile 32x64, 8 n-tiles per CTA.
// MODE 0 (QKV): B = fp32 X (pixel layout) via split LDG+cvt+STS; out = fp16 window layout.
// MODE 1 (proj): B = fp16 g_atth via cp.async; out = fp32 pixel layout + residual.
template<int MODE>
__global__ void __launch_bounds__(256) gemm8(
    const unsigned* __restrict__ Af,
    const float* __restrict__ bias,
    const void* __restrict__ Bsrc,
    const float* __restrict__ resid,
    void* __restrict__ outp,
    int Mvalid)
{
    extern __shared__ char sm[];
    const int tid = threadIdx.x;
    const int wid = tid >> 5, lane = tid & 31;
    const int wm = wid >> 1, wn = wid & 1;
    const int bz = blockIdx.z;
    const int m0 = blockIdx.x * 128;
    const uint32_t sb = smem_u32(sm);

    // ---- resident A via cp.async ----
    {
        const char* Ag = (const char*)(Af + (size_t)blockIdx.x * APM);
        #pragma unroll
        for (int i = 0; i < 12; i++)
            cpa16(sb + (uint32_t)((i * 256 + tid) * 16), Ag + (i * 256 + tid) * 16);
    }

    // ---- initial B0 into buf 0 ----
    const int n0_first = blockIdx.y * TILES_PER_CTA * 128;
    if (MODE == 0) {
        const float* Xb = (const float*)Bsrc + (size_t)bz * KDIM * HW + n0_first;
        #pragma unroll
        for (int i = 0; i < 12; i++) {
            int c = tid + i * 256;
            int row = c >> 4, col8 = (c & 15) * 8;
            const float* src = Xb + (size_t)row * HW + col8;
            float4 p0 = *(const float4*)src;
            float4 p1 = *(const float4*)(src + 4);
            uint4 t;
            t.x = pack_h2(p0.x, p0.y); t.y = pack_h2(p0.z, p0.w);
            t.z = pack_h2(p1.x, p1.y); t.w = pack_h2(p1.z, p1.w);
            *(uint4*)(sm + SB_TILE + (row * BPADH + col8) * 2) = t;
        }
    } else {
        const __half* Bh = (const __half*)Bsrc;
        int py = n0_first >> 8;
        #pragma unroll
        for (int i = 0; i < 12; i++) {
            int c = tid + i * 256;
            int row = c >> 4, g = c & 15;
            int px = (n0_first & 255) + g * 8;
            int winb = ((py >> 3) << 5) + (px >> 3);
            int tok0 = (py & 7) * 8;
            cpa16(sb + SB_TILE + (uint32_t)(row * BPADH + g * 8) * 2,
                  Bh + ((size_t)(bz * NWIN + winb) * CDIM + row) * 64 + tok0);
        }
    }
    asm volatile("cp.async.commit_group;");
    asm volatile("cp.async.wait_group 0;" ::: "memory");
    __syncthreads();

    const int lrow = (lane & 7) + ((lane >> 3) & 1) * 8;
    const int lcol = ((lane >> 4) & 1) * 8;
    const int gr = lane >> 2;
    const int qc = (lane & 3) * 2;

    #pragma unroll 1
    for (int it = 0; it < TILES_PER_CTA; it++) {
        const int buf = it & 1;
        const int nb  = buf ^ 1;
        const int n0 = (blockIdx.y * TILES_PER_CTA + it) * 128;
        const int py = n0 >> 8;
        const uint32_t Bb = sb + SB_TILE + buf * BBYTES
                          + (uint32_t)((lrow * BPADH + wn * 64 + lcol) * 2);
        const bool pre = (it + 1 < TILES_PER_CTA);
        const int n0n = n0 + 128;

        if (MODE == 1 && pre) {
            const __half* Bh = (const __half*)Bsrc;
            int pyn = n0n >> 8;
            #pragma unroll
            for (int i = 0; i < 12; i++) {
                int c = tid + i * 256;
                int row = c >> 4, g = c & 15;
                int px = (n0n & 255) + g * 8;
                int winb = ((pyn >> 3) << 5) + (px >> 3);
                int tok0 = (pyn & 7) * 8;
                cpa16(sb + SB_TILE + nb * BBYTES + (uint32_t)(row * BPADH + g * 8) * 2,
                      Bh + ((size_t)(bz * NWIN + winb) * CDIM + row) * 64 + tok0);
            }
            asm volatile("cp.async.commit_group;");
        }

        float acc[2][8][4];
        #pragma unroll
        for (int mf = 0; mf < 2; mf++)
            #pragma unroll
            for (int nf = 0; nf < 8; nf++)
                #pragma unroll
                for (int j = 0; j < 4; j++) acc[mf][nf][j] = 0.f;

        if (MODE == 0 && pre) {
            const float* Xn = (const float*)Bsrc + (size_t)bz * KDIM * HW + n0n;
            float4 pf[12];
            // chunk A: rows 0..95 of next tile
            #pragma unroll
            for (int i = 0; i < 6; i++) {
                int c = tid + i * 256;
                int row = c >> 4, col8 = (c & 15) * 8;
                pf[2 * i]     = *(const float4*)(Xn + (size_t)row * HW + col8);
                pf[2 * i + 1] = *(const float4*)(Xn + (size_t)row * HW + col8 + 4);
            }
            #pragma unroll
            for (int kk = 0; kk < 6; kk++) gemm_kk(sb, Bb, wm, lane, acc, kk);
            #pragma unroll
            for (int i = 0; i < 6; i++) {
                int c = tid + i * 256;
                int row = c >> 4, col8 = (c & 15) * 8;
                uint4 t;
                t.x = pack_h2(pf[2 * i].x, pf[2 * i].y);
                t.y = pack_h2(pf[2 * i].z, pf[2 * i].w);
                t.z = pack_h2(pf[2 * i + 1].x, pf[2 * i + 1].y);
                t.w = pack_h2(pf[2 * i + 1].z, pf[2 * i + 1].w);
                *(uint4*)(sm + SB_TILE + nb * BBYTES + (row * BPADH + col8) * 2) = t;
            }
            // chunk B: rows 96..191 of next tile
            #pragma unroll
            for (int i = 0; i < 6; i++) {
                int c = tid + (i + 6) * 256;
                int row = c >> 4, col8 = (c & 15) * 8;
                pf[2 * i]     = *(const float4*)(Xn + (size_t)row * HW + col8);
                pf[2 * i + 1] = *(const float4*)(Xn + (size_t)row * HW + col8 + 4);
            }
            #pragma unroll
            for (int kk = 6; kk < 12; kk++) gemm_kk(sb, Bb, wm, lane, acc, kk);
            #pragma unroll
            for (int i = 0; i < 6; i++) {
                int c = tid + (i + 6) * 256;
                int row = c >> 4, col8 = (c & 15) * 8;
                uint4 t;
                t.x = pack_h2(pf[2 * i].x, pf[2 * i].y);
                t.y = pack_h2(pf[2 * i].z, pf[2 * i].w);
                t.z = pack_h2(pf[2 * i + 1].x, pf[2 * i + 1].y);
                t.w = pack_h2(pf[2 * i + 1].z, pf[2 * i + 1].w);
                *(uint4*)(sm + SB_TILE + nb * BBYTES + (row * BPADH + col8) * 2) = t;
            }
        } else {
            #pragma unroll
            for (int kk = 0; kk < 12; kk++) gemm_kk(sb, Bb, wm, lane, acc, kk);
        }

        // ---- epilogue for this tile ----
        if (MODE == 0) {
            __half* outW = (__half*)outp + (size_t)bz * NWIN * 576 * 64;
            #pragma unroll
            for (int mf = 0; mf < 2; mf++) {
                #pragma unroll
                for (int hh = 0; hh < 2; hh++) {
                    int m = m0 + wm * 32 + mf * 16 + gr + hh * 8;
                    if (m < Mvalid) {
                        float bv = bias[m];
                        #pragma unroll
                        for (int nf = 0; nf < 8; nf++) {
                            int px = (n0 & 255) + wn * 64 + nf * 8 + qc;
                            int win = ((py >> 3) << 5) + (px >> 3);
                            int tok = (py & 7) * 8 + (px & 7);
                            __half2 o = __floats2half2_rn(acc[mf][nf][hh * 2 + 0] + bv,
                                                          acc[mf][nf][hh * 2 + 1] + bv);
                            *(__half2*)&outW[((size_t)win * 576 + m) * 64 + tok] = o;
                        }
                    }
                }
            }
        } else {
            float* outB = (float*)outp + (size_t)bz * CDIM * HW;
            const float* resB = resid + (size_t)bz * CDIM * HW;
            #pragma unroll
            for (int mf = 0; mf < 2; mf++) {
                #pragma unroll
                for (int hh = 0; hh < 2; hh++) {
                    int m = m0 + wm * 32 + mf * 16 + gr + hh * 8;
                    if (m < Mvalid) {
                        float bv = bias[m];
                        float* orow = outB + (size_t)m * HW + n0 + wn * 64 + qc;
                        const float* rrow = resB + (size_t)m * HW + n0 + wn * 64 + qc;
                        #pragma unroll
                        for (int nf = 0; nf < 8; nf++) {
                            float2 o;
                            o.x = acc[mf][nf][hh * 2 + 0] + bv;
                            o.y = acc[mf][nf][hh * 2 + 1] + bv;
                            float2 rv = *(const float2*)(rrow + nf * 8);
                            o.x += rv.x; o.y += rv.y;
                            *(float2*)(orow + nf * 8) = o;
                        }
                    }
                }
            }
        }

        if (MODE == 1 && pre)
            asm volatile("cp.async.wait_group 0;" ::: "memory");
        __syncthreads();
    }
}

// ---------------- kernel 3: tensor-core attention on window-native fp16 (R9, proven) ----------------
__global__ void __launch_bounds__(128) attn4(const float* __restrict__ logit_scale)
{
    __shared__ __half qs_[32 * 72];
    __shared__ __half ks_[32 * 72];
    __shared__ __half vs_[24 * 72];
    __shared__ __half os_[24 * 72];
    __shared__ float qn[64], kn[64];

    const int tid  = threadIdx.x;
    const int lane = tid & 31;
    const int wr   = tid >> 5;
    const int win  = blockIdx.x;
    const int h    = blockIdx.y;
    const int bz   = blockIdx.z;

    const float LN100 = 4.6051701860f;
    const float scale_h = expf(fminf(logit_scale[h], LN100));

    const __half* gq = g_qkvh + ((size_t)(bz * NWIN + win) * 576 + h * HD) * 64;
    #pragma unroll
    for (int pass = 0; pass < 5; pass++) {
        int idx = tid + pass * 128;
        if (idx < 576) {
            int arr = idx / 192, rem = idx % 192;
            int d = rem >> 3, tg = rem & 7;
            uint4 val = *(const uint4*)(gq + (size_t)arr * 192 * 64 + d * 64 + tg * 8);
            __half* dst = (arr == 0) ? qs_ : (arr == 1) ? ks_ : vs_;
            *(uint4*)&dst[d * 72 + tg * 8] = val;
        }
    }
    {
        int arr2 = tid >> 6, rr = (tid >> 3) & 7, tg = tid & 7;
        __half* dst = arr2 ? ks_ : qs_;
        *(uint4*)&dst[(24 + rr) * 72 + tg * 8] = make_uint4(0, 0, 0, 0);
    }
    __syncthreads();

    {
        int t = tid & 63;
        const __half* col = (tid < 64) ? qs_ : ks_;
        float ss = 0.f;
        #pragma unroll
        for (int d = 0; d < HD; d++) {
            float f = __half2float(col[d * 72 + t]);
            ss = fmaf(f, f, ss);
        }
        float inv = 1.f / fmaxf(sqrtf(ss), 1e-12f);
        if (tid < 64) qn[t] = inv * scale_h; else kn[t] = inv;
    }
    __syncthreads();

    const uint32_t qb = smem_u32(qs_), kb = smem_u32(ks_), vb = smem_u32(vs_);
    const int gr = lane >> 2;
    const int qc = (lane & 3) * 2;
    const int r0 = wr * 16 + gr, r1 = r0 + 8;

    float S[8][4];
    #pragma unroll
    for (int nb = 0; nb < 8; nb++)
        #pragma unroll
        for (int j = 0; j < 4; j++) S[nb][j] = 0.f;

    #pragma unroll
    for (int ks = 0; ks < 2; ks++) {
        uint32_t a[4];
        ldmx4t(a, qb + (uint32_t)(((ks * 16 + (lane & 7) + ((lane >> 4) & 1) * 8) * 72
                                   + wr * 16 + ((lane >> 3) & 1) * 8) * 2));
        #pragma unroll
        for (int nbp = 0; nbp < 4; nbp++) {
            uint32_t b[4];
            ldmx4t(b, kb + (uint32_t)(((ks * 16 + (lane & 7) + ((lane >> 3) & 1) * 8) * 72
                                       + nbp * 16 + ((lane >> 4) & 1) * 8) * 2));
            mma_f16(S[nbp * 2],     a, &b[0]);
            mma_f16(S[nbp * 2 + 1], a, &b[2]);
        }
    }

    const float qn0 = qn[r0], qn1 = qn[r1];
    #pragma unroll
    for (int nb = 0; nb < 8; nb++) {
        int c0 = nb * 8 + qc;
        float k0v = kn[c0], k1v = kn[c0 + 1];
        float2 b0 = *(const float2*)&g_bias[(h * 64 + r0) * 64 + c0];
        float2 b1 = *(const float2*)&g_bias[(h * 64 + r1) * 64 + c0];
        S[nb][0] = S[nb][0] * qn0 * k0v + b0.x;
        S[nb][1] = S[nb][1] * qn0 * k1v + b0.y;
        S[nb][2] = S[nb][2] * qn1 * k0v + b1.x;
        S[nb][3] = S[nb][3] * qn1 * k1v + b1.y;
    }

    float mx0 = -1e30f, mx1 = -1e30f;
    #pragma unroll
    for (int nb = 0; nb < 8; nb++) {
        mx0 = fmaxf(mx0, fmaxf(S[nb][0], S[nb][1]));
        mx1 = fmaxf(mx1, fmaxf(S[nb][2], S[nb][3]));
    }
    mx0 = fmaxf(mx0, __shfl_xor_sync(0xffffffffu, mx0, 1));
    mx0 = fmaxf(mx0, __shfl_xor_sync(0xffffffffu, mx0, 2));
    mx1 = fmaxf(mx1, __shfl_xor_sync(0xffffffffu, mx1, 1));
    mx1 = fmaxf(mx1, __shfl_xor_sync(0xffffffffu, mx1, 2));
    float s0 = 0.f, s1 = 0.f;
    #pragma unroll
    for (int nb = 0; nb < 8; nb++) {
        S[nb][0] = __expf(S[nb][0] - mx0); s0 += S[nb][0];
        S[nb][1] = __expf(S[nb][1] - mx0); s0 += S[nb][1];
        S[nb][2] = __expf(S[nb][2] - mx1); s1 += S[nb][2];
        S[nb][3] = __expf(S[nb][3] - mx1); s1 += S[nb][3];
    }
    s0 += __shfl_xor_sync(0xffffffffu, s0, 1);
    s0 += __shfl_xor_sync(0xffffffffu, s0, 2);
    s1 += __shfl_xor_sync(0xffffffffu, s1, 1);
    s1 += __shfl_xor_sync(0xffffffffu, s1, 2);
    float pinv0 = 1.f / s0, pinv1 = 1.f / s1;
    #pragma unroll
    for (int nb = 0; nb < 8; nb++) {
        S[nb][0] *= pinv0; S[nb][1] *= pinv0;
        S[nb][2] *= pinv1; S[nb][3] *= pinv1;
    }

    float O[3][4];
    #pragma unroll
    for (int nb3 = 0; nb3 < 3; nb3++)
        #pragma unroll
        for (int j = 0; j < 4; j++) O[nb3][j] = 0.f;

    #pragma unroll
    for (int kt = 0; kt < 4; kt++) {
        uint32_t a[4];
        a[0] = pack_h2(S[2 * kt][0],     S[2 * kt][1]);
        a[1] = pack_h2(S[2 * kt][2],     S[2 * kt][3]);
        a[2] = pack_h2(S[2 * kt + 1][0], S[2 * kt + 1][1]);
        a[3] = pack_h2(S[2 * kt + 1][2], S[2 * kt + 1][3]);
        uint32_t b[4];
        ldmx4(b, vb + (uint32_t)((((lane & 7) + ((lane >> 4) & 1) * 8) * 72
                                   + kt * 16 + ((lane >> 3) & 1) * 8) * 2));
        mma_f16(O[0], a, &b[0]);
        mma_f16(O[1], a, &b[2]);
        uint32_t b2[2];
        ldmx2(b2, vb + (uint32_t)(((16 + (lane & 7)) * 72
                                    + kt * 16 + (((lane & 15) >> 3) & 1) * 8) * 2));
        mma_f16(O[2], a, b2);
    }

    #pragma unroll
    for (int nb3 = 0; nb3 < 3; nb3++) {
        int d = nb3 * 8 + qc;
        os_[d * 72 + r0]       = __float2half(O[nb3][0]);
        os_[(d + 1) * 72 + r0] = __float2half(O[nb3][1]);
        os_[d * 72 + r1]       = __float2half(O[nb3][2]);
        os_[(d + 1) * 72 + r1] = __float2half(O[nb3][3]);
    }
    __syncthreads();

    __half* ga = g_atth + ((size_t)(bz * NWIN + win) * CDIM + h * HD) * 64;
    #pragma unroll
    for (int pass = 0; pass < 2; pass++) {
        int idx = tid + pass * 128;
        if (idx < 192) {
            int d = idx >> 3, tg = idx & 7;
            *(uint4*)(ga + d * 64 + tg * 8) = *(uint4*)&os_[d * 72 + tg * 8];
        }
    }
}

// ---------------- launch ----------------
extern "C" void kernel_launch(void* const* d_in, const int* in_sizes, int n_in,
                              void* d_out, int out_size)
{
    const float* x        = (const float*)d_in[0];
    const float* qkv_w    = (const float*)d_in[2];
    const float* q_bias   = (const float*)d_in[3];
    const float* v_bias   = (const float*)d_in[4];
    const float* lscale   = (const float*)d_in[5];
    const float* cpb_w1   = (const float*)d_in[6];
    const float* cpb_b1   = (const float*)d_in[7];
    const float* cpb_w2   = (const float*)d_in[8];
    const float* proj_w   = (const float*)d_in[9];
    const float* proj_b   = (const float*)d_in[10];
    float* out = (float*)d_out;

    __half *qkv_buf, *att_buf;
    float *bq, *bp;
    unsigned *wqf, *wpf;
    cudaGetSymbolAddress((void**)&qkv_buf, g_qkvh);
    cudaGetSymbolAddress((void**)&att_buf, g_atth);
    cudaGetSymbolAddress((void**)&wqf, g_wqf);
    cudaGetSymbolAddress((void**)&wpf, g_wpf);
    cudaGetSymbolAddress((void**)&bq, g_bq);
    cudaGetSymbolAddress((void**)&bp, g_bp);

    cudaFuncSetAttribute(gemm8<0>, cudaFuncAttributeMaxDynamicSharedMemorySize, SMEM_G);
    cudaFuncSetAttribute(gemm8<1>, cudaFuncAttributeMaxDynamicSharedMemorySize, SMEM_G);

    bias_kernel<<<1, 256>>>(cpb_w1, cpb_b1, cpb_w2);
    prep_kernel<<<128, 256>>>(qkv_w, q_bias, v_bias, proj_w, proj_b);

    // QKV: 5 m-tiles x 64 CTA-columns (8 n-tiles each) x 4 batch
    gemm8<0><<<dim3(MQ / 128, (HW / 128) / TILES_PER_CTA, NB), 256, SMEM_G>>>(
        wqf, bq, x, nullptr, qkv_buf, 576);

    // windowed cosine attention on window-native fp16
    attn4<<<dim3(NWIN, NH, NB), 128>>>(lscale);

    // proj + bias + residual -> fp32 output
    gemm8<1><<<dim3(MP / 128, (HW / 128) / TILES_PER_CTA, NB), 256, SMEM_G>>>(
        wpf, bp, att_buf, x, out, 192);
}

// round 13
// speedup vs baseline: 1.2425x; 1.2425x over previous
#include <cuda_runtime.h>
#include <cuda_fp16.h>
#include <math.h>
#include <cstdint>

#define NH   8
#define HD   24
#define CDIM 192
#define HW   65536   // 256*256
#define NB   4
#define KDIM 192
#define MQ   640     // qkv rows padded to 5*128 (576 valid)
#define MP   256
#define NWIN 1024    // 32x32 windows

#define BPADH  136
#define APM    12288
// gemm9 smem (bytes): A frags @0 : 49152 ; B fp16 tile @49152 : 52224 -> 101376 total
#define SB_TILE 49152
#define SMEM_G  101376
#define TILES_PER_CTA 8

// ---------------- device scratch (fp16 window-native intermediates) ----------------
__device__ __half   g_qkvh[(size_t)NB * NWIN * 576 * 64];   // (B, win, ch, tok)
__device__ __half   g_atth[(size_t)NB * NWIN * CDIM * 64];  // (B, win, ch, tok)
__device__ float    g_bias[NH * 64 * 64];
__device__ unsigned g_wqf[5 * APM];
__device__ unsigned g_wpf[2 * APM];
__device__ float    g_bq[MQ];
__device__ float    g_bp[MP];

// ---------------- helpers ----------------
__device__ __forceinline__ uint32_t smem_u32(const void* p) {
    uint32_t a;
    asm("{ .reg .u64 t; cvta.to.shared.u64 t, %1; cvt.u32.u64 %0, t; }" : "=r"(a) : "l"(p));
    return a;
}
__device__ __forceinline__ void cpa16(uint32_t dst, const void* src) {
    asm volatile("cp.async.cg.shared.global [%0], [%1], 16;" :: "r"(dst), "l"(src));
}
__device__ __forceinline__ void lds128(uint32_t* r, uint32_t a) {
    asm volatile("ld.shared.v4.b32 {%0,%1,%2,%3}, [%4];"
                 : "=r"(r[0]), "=r"(r[1]), "=r"(r[2]), "=r"(r[3]) : "r"(a));
}
__device__ __forceinline__ void ldmx4(uint32_t* r, uint32_t a) {
    asm volatile("ldmatrix.sync.aligned.m8n8.x4.shared.b16 {%0,%1,%2,%3}, [%4];"
                 : "=r"(r[0]), "=r"(r[1]), "=r"(r[2]), "=r"(r[3]) : "r"(a));
}
__device__ __forceinline__ void ldmx4t(uint32_t* r, uint32_t a) {
    asm volatile("ldmatrix.sync.aligned.m8n8.x4.trans.shared.b16 {%0,%1,%2,%3}, [%4];"
                 : "=r"(r[0]), "=r"(r[1]), "=r"(r[2]), "=r"(r[3]) : "r"(a));
}
__device__ __forceinline__ void ldmx2(uint32_t* r, uint32_t a) {
    asm volatile("ldmatrix.sync.aligned.m8n8.x2.shared.b16 {%0,%1}, [%2];"
                 : "=r"(r[0]), "=r"(r[1]) : "r"(a));
}
__device__ __forceinline__ void mma_f16(float* c, const uint32_t* a, const uint32_t* b) {
    asm volatile("mma.sync.aligned.m16n8k16.row.col.f32.f16.f16.f32 "
                 "{%0,%1,%2,%3}, {%4,%5,%6,%7}, {%8,%9}, {%0,%1,%2,%3};"
                 : "+f"(c[0]), "+f"(c[1]), "+f"(c[2]), "+f"(c[3])
                 : "r"(a[0]), "r"(a[1]), "r"(a[2]), "r"(a[3]), "r"(b[0]), "r"(b[1]));
}
__device__ __forceinline__ uint32_t pack_h2(float lo, float hi) {
    __half2 h = __floats2half2_rn(lo, hi);
    return *(uint32_t*)&h;
}

// ---------------- kernel 1: CPB bias table ----------------
__global__ void bias_kernel(const float* __restrict__ w1, const float* __restrict__ b1,
                            const float* __restrict__ w2)
{
    __shared__ float table[225][NH];
    int tid = threadIdx.x;

    if (tid < 225) {
        int a = tid / 15, b = tid % 15;
        const float inv_l8 = 1.0f / log2f(8.0f);
        float ca = (float)(a - 7) / 7.0f * 8.0f;
        float cb = (float)(b - 7) / 7.0f * 8.0f;
        float r0 = (ca == 0.f) ? 0.f : copysignf(log2f(fabsf(ca) + 1.0f) * inv_l8, ca);
        float r1 = (cb == 0.f) ? 0.f : copysignf(log2f(fabsf(cb) + 1.0f) * inv_l8, cb);
        float acc[NH];
        #pragma unroll
        for (int h = 0; h < NH; h++) acc[h] = 0.f;
        for (int j = 0; j < 512; j++) {
            float hv = fmaf(r0, w1[j], fmaf(r1, w1[512 + j], b1[j]));
            hv = fmaxf(hv, 0.f);
            #pragma unroll
            for (int h = 0; h < NH; h++) acc[h] = fmaf(hv, w2[j * NH + h], acc[h]);
        }
        #pragma unroll
        for (int h = 0; h < NH; h++) table[tid][h] = acc[h];
    }
    __syncthreads();

    for (int idx = tid; idx < NH * 64 * 64; idx += blockDim.x) {
        int h  = idx / (64 * 64);
        int nm = idx % (64 * 64);
        int n = nm / 64, m = nm % 64;
        int di = (n >> 3) - (m >> 3) + 7;
        int dj = (n & 7) - (m & 7) + 7;
        float t = table[di * 15 + dj][h];
        g_bias[idx] = 16.f / (1.f + expf(-t));
    }
}

// ---------------- kernel 1b: pack weights into fp16 m16n8k16 fragment layout ----------------
__global__ void prep_kernel(const float* __restrict__ qkv_w, const float* __restrict__ qb,
                            const float* __restrict__ vb,
                            const float* __restrict__ proj_w, const float* __restrict__ pb)
{
    int i = blockIdx.x * blockDim.x + threadIdx.x;
    int stride = gridDim.x * blockDim.x;

    for (int idx = i; idx < 5 * APM; idx += stride) {
        int mt  = idx / APM;
        int r   = idx % APM;
        int kst = r / 2048;
        int r2  = r % 2048;
        int slot = r2 & 3, lane = (r2 >> 2) & 31, mf = (r2 >> 7) & 7, ks = (r2 >> 10) & 1;
        int m = mt * 128 + mf * 16 + (lane >> 2) + (slot & 1) * 8;
        int k = kst * 32 + ks * 16 + (lane & 3) * 2 + ((slot >> 1) & 1) * 8;
        float v0 = (m < 576) ? qkv_w[m * KDIM + k]     : 0.f;
        float v1 = (m < 576) ? qkv_w[m * KDIM + k + 1] : 0.f;
        g_wqf[idx] = pack_h2(v0, v1);
    }
    for (int idx = i; idx < 2 * APM; idx += stride) {
        int mt  = idx / APM;
        int r   = idx % APM;
        int kst = r / 2048;
        int r2  = r % 2048;
        int slot = r2 & 3, lane = (r2 >> 2) & 31, mf = (r2 >> 7) & 7, ks = (r2 >> 10) & 1;
        int m = mt * 128 + mf * 16 + (lane >> 2) + (slot & 1) * 8;
        int k = kst * 32 + ks * 16 + (lane & 3) * 2 + ((slot >> 1) & 1) * 8;
        float v0 = (m < 192) ? proj_w[m * KDIM + k]     : 0.f;
        float v1 = (m < 192) ? proj_w[m * KDIM + k + 1] : 0.f;
        g_wpf[idx] = pack_h2(v0, v1);
    }
    if (i < MQ) {
        float v = 0.f;
        if (i < 192)                  v = qb[i];
        else if (i >= 384 && i < 576) v = vb[i - 384];
        g_bq[i] = v;
    }
    if (i < MP) g_bp[i] = (i < 192) ? pb[i] : 0.f;
}

// ---------------- kernel 2/4: gemm9 = gemm7 + resident-A tile loop, 2 CTA/SM ----------------
// 256 threads (8 warps: wm 0..3, wn 0..1), warp tile 32x64, 8 n-tiles per CTA.
// MODE 0 (QKV): B = fp32 X (pixel layout) via LDG+cvt+STS; out = fp16 window layout.
// MODE 1 (proj): B = fp16 g_atth via cp.async; out = fp32 pixel layout + residual.
template<int MODE>
__global__ void __launch_bounds__(256, 2) gemm9(
    const unsigned* __restrict__ Af,
    const float* __restrict__ bias,
    const void* __restrict__ Bsrc,
    const float* __restrict__ resid,
    void* __restrict__ outp,
    int Mvalid)
{
    extern __shared__ char sm[];
    const int tid = threadIdx.x;
    const int wid = tid >> 5, lane = tid & 31;
    const int wm = wid >> 1, wn = wid & 1;
    const int bz = blockIdx.z;
    const int m0 = blockIdx.x * 128;
    const uint32_t sb = smem_u32(sm);

    // ---- resident A via cp.async (once per CTA) ----
    {
        const char* Ag = (const char*)(Af + (size_t)blockIdx.x * APM);
        #pragma unroll
        for (int i = 0; i < 12; i++)
            cpa16(sb + (uint32_t)((i * 256 + tid) * 16), Ag + (i * 256 + tid) * 16);
        asm volatile("cp.async.commit_group;");
    }

    const int lrow = (lane & 7) + ((lane >> 3) & 1) * 8;
    const int lcol = ((lane >> 4) & 1) * 8;
    const int gr = lane >> 2;
    const int qc = (lane & 3) * 2;
    const uint32_t Bb = sb + SB_TILE + (uint32_t)((lrow * BPADH + wn * 64 + lcol) * 2);

    #pragma unroll 1
    for (int it = 0; it < TILES_PER_CTA; it++) {
        const int n0 = (blockIdx.y * TILES_PER_CTA + it) * 128;
        const int py = n0 >> 8;

        // ---- load B tile ----
        if (MODE == 0) {
            const float* Xb = (const float*)Bsrc + (size_t)bz * KDIM * HW + n0;
            #pragma unroll
            for (int i = 0; i < 12; i++) {
                int c = tid + i * 256;
                int row = c >> 4, col8 = (c & 15) * 8;
                const float* src = Xb + (size_t)row * HW + col8;
                float4 p0 = *(const float4*)src;
                float4 p1 = *(const float4*)(src + 4);
                uint4 t;
                t.x = pack_h2(p0.x, p0.y); t.y = pack_h2(p0.z, p0.w);
                t.z = pack_h2(p1.x, p1.y); t.w = pack_h2(p1.z, p1.w);
                *(uint4*)(sm + SB_TILE + (row * BPADH + col8) * 2) = t;
            }
            if (it == 0)
                asm volatile("cp.async.wait_group 0;" ::: "memory");  // A ready
        } else {
            const __half* Bh = (const __half*)Bsrc;
            #pragma unroll
            for (int i = 0; i < 12; i++) {
                int c = tid + i * 256;
                int row = c >> 4, g = c & 15;
                int px = (n0 & 255) + g * 8;
                int winb = ((py >> 3) << 5) + (px >> 3);
                int tok0 = (py & 7) * 8;
                cpa16(sb + SB_TILE + (uint32_t)(row * BPADH + g * 8) * 2,
                      Bh + ((size_t)(bz * NWIN + winb) * CDIM + row) * 64 + tok0);
            }
            asm volatile("cp.async.commit_group;");
            asm volatile("cp.async.wait_group 0;" ::: "memory");      // B (and A on it=0)
        }
        __syncthreads();

        // ---- compute: 12 k-steps ----
        float acc[2][8][4];
        #pragma unroll
        for (int mf = 0; mf < 2; mf++)
            #pragma unroll
            for (int nf = 0; nf < 8; nf++)
                #pragma unroll
                for (int j = 0; j < 4; j++) acc[mf][nf][j] = 0.f;

        #pragma unroll
        for (int kk = 0; kk < 12; kk++) {
            uint32_t a[2][4];
            const uint32_t Ab = sb + (kk >> 1) * 8192;
            lds128(a[0], Ab + (((kk & 1) * 8 + wm * 2 + 0) * 32 + lane) * 16);
            lds128(a[1], Ab + (((kk & 1) * 8 + wm * 2 + 1) * 32 + lane) * 16);
            uint32_t bm[4][4];
            #pragma unroll
            for (int nfp = 0; nfp < 4; nfp++)
                ldmx4t(bm[nfp], Bb + (uint32_t)((kk * 16 * BPADH + nfp * 16) * 2));
            #pragma unroll
            for (int mf = 0; mf < 2; mf++)
                #pragma unroll
                for (int nf = 0; nf < 8; nf++)
                    mma_f16(acc[mf][nf], a[mf], &bm[nf >> 1][(nf & 1) * 2]);
        }

        // ---- epilogue for this tile ----
        if (MODE == 0) {
            __half* outW = (__half*)outp + (size_t)bz * NWIN * 576 * 64;
            #pragma unroll
            for (int mf = 0; mf < 2; mf++) {
                #pragma unroll
                for (int hh = 0; hh < 2; hh++) {
                    int m = m0 + wm * 32 + mf * 16 + gr + hh * 8;
                    if (m < Mvalid) {
                        float bv = bias[m];
                        #pragma unroll
                        for (int nf = 0; nf < 8; nf++) {
                            int px = (n0 & 255) + wn * 64 + nf * 8 + qc;
                            int win = ((py >> 3) << 5) + (px >> 3);
                            int tok = (py & 7) * 8 + (px & 7);
                            __half2 o = __floats2half2_rn(acc[mf][nf][hh * 2 + 0] + bv,
                                                          acc[mf][nf][hh * 2 + 1] + bv);
                            *(__half2*)&outW[((size_t)win * 576 + m) * 64 + tok] = o;
                        }
                    }
                }
            }
        } else {
            float* outB = (float*)outp + (size_t)bz * CDIM * HW;
            const float* resB = resid + (size_t)bz * CDIM * HW;
            #pragma unroll
            for (int mf = 0; mf < 2; mf++) {
                #pragma unroll
                for (int hh = 0; hh < 2; hh++) {
                    int m = m0 + wm * 32 + mf * 16 + gr + hh * 8;
                    if (m < Mvalid) {
                        float bv = bias[m];
                        float* orow = outB + (size_t)m * HW + n0 + wn * 64 + qc;
                        const float* rrow = resB + (size_t)m * HW + n0 + wn * 64 + qc;
                        #pragma unroll
                        for (int nf = 0; nf < 8; nf++) {
                            float2 o;
                            o.x = acc[mf][nf][hh * 2 + 0] + bv;
                            o.y = acc[mf][nf][hh * 2 + 1] + bv;
                            float2 rv = *(const float2*)(rrow + nf * 8);
                            o.x += rv.x; o.y += rv.y;
                            *(float2*)(orow + nf * 8) = o;
                        }
                    }
                }
            }
        }
        __syncthreads();   // protect B tile before next iteration's overwrite
    }
}

// ---------------- kernel 3: tensor-core attention on window-native fp16 (R9, proven) ----------------
__global__ void __launch_bounds__(128) attn4(const float* __restrict__ logit_scale)
{
    __shared__ __half qs_[32 * 72];
    __shared__ __half ks_[32 * 72];
    __shared__ __half vs_[24 * 72];
    __shared__ __half os_[24 * 72];
    __shared__ float qn[64], kn[64];

    const int tid  = threadIdx.x;
    const int lane = tid & 31;
    const int wr   = tid >> 5;
    const int win  = blockIdx.x;
    const int h    = blockIdx.y;
    const int bz   = blockIdx.z;

    const float LN100 = 4.6051701860f;
    const float scale_h = expf(fminf(logit_scale[h], LN100));

    const __half* gq = g_qkvh + ((size_t)(bz * NWIN + win) * 576 + h * HD) * 64;
    #pragma unroll
    for (int pass = 0; pass < 5; pass++) {
        int idx = tid + pass * 128;
        if (idx < 576) {
            int arr = idx / 192, rem = idx % 192;
            int d = rem >> 3, tg = rem & 7;
            uint4 val = *(const uint4*)(gq + (size_t)arr * 192 * 64 + d * 64 + tg * 8);
            __half* dst = (arr == 0) ? qs_ : (arr == 1) ? ks_ : vs_;
            *(uint4*)&dst[d * 72 + tg * 8] = val;
        }
    }
    {
        int arr2 = tid >> 6, rr = (tid >> 3) & 7, tg = tid & 7;
        __half* dst = arr2 ? ks_ : qs_;
        *(uint4*)&dst[(24 + rr) * 72 + tg * 8] = make_uint4(0, 0, 0, 0);
    }
    __syncthreads();

    {
        int t = tid & 63;
        const __half* col = (tid < 64) ? qs_ : ks_;
        float ss = 0.f;
        #pragma unroll
        for (int d = 0; d < HD; d++) {
            float f = __half2float(col[d * 72 + t]);
            ss = fmaf(f, f, ss);
        }
        float inv = 1.f / fmaxf(sqrtf(ss), 1e-12f);
        if (tid < 64) qn[t] = inv * scale_h; else kn[t] = inv;
    }
    __syncthreads();

    const uint32_t qb = smem_u32(qs_), kb = smem_u32(ks_), vb = smem_u32(vs_);
    const int gr = lane >> 2;
    const int qc = (lane & 3) * 2;
    const int r0 = wr * 16 + gr, r1 = r0 + 8;

    float S[8][4];
    #pragma unroll
    for (int nb = 0; nb < 8; nb++)
        #pragma unroll
        for (int j = 0; j < 4; j++) S[nb][j] = 0.f;

    #pragma unroll
    for (int ks = 0; ks < 2; ks++) {
        uint32_t a[4];
        ldmx4t(a, qb + (uint32_t)(((ks * 16 + (lane & 7) + ((lane >> 4) & 1) * 8) * 72
                                   + wr * 16 + ((lane >> 3) & 1) * 8) * 2));
        #pragma unroll
        for (int nbp = 0; nbp < 4; nbp++) {
            uint32_t b[4];
            ldmx4t(b, kb + (uint32_t)(((ks * 16 + (lane & 7) + ((lane >> 3) & 1) * 8) * 72
                                       + nbp * 16 + ((lane >> 4) & 1) * 8) * 2));
            mma_f16(S[nbp * 2],     a, &b[0]);
            mma_f16(S[nbp * 2 + 1], a, &b[2]);
        }
    }

    const float qn0 = qn[r0], qn1 = qn[r1];
    #pragma unroll
    for (int nb = 0; nb < 8; nb++) {
        int c0 = nb * 8 + qc;
        float k0v = kn[c0], k1v = kn[c0 + 1];
        float2 b0 = *(const float2*)&g_bias[(h * 64 + r0) * 64 + c0];
        float2 b1 = *(const float2*)&g_bias[(h * 64 + r1) * 64 + c0];
        S[nb][0] = S[nb][0] * qn0 * k0v + b0.x;
        S[nb][1] = S[nb][1] * qn0 * k1v + b0.y;
        S[nb][2] = S[nb][2] * qn1 * k0v + b1.x;
        S[nb][3] = S[nb][3] * qn1 * k1v + b1.y;
    }

    float mx0 = -1e30f, mx1 = -1e30f;
    #pragma unroll
    for (int nb = 0; nb < 8; nb++) {
        mx0 = fmaxf(mx0, fmaxf(S[nb][0], S[nb][1]));
        mx1 = fmaxf(mx1, fmaxf(S[nb][2], S[nb][3]));
    }
    mx0 = fmaxf(mx0, __shfl_xor_sync(0xffffffffu, mx0, 1));
    mx0 = fmaxf(mx0, __shfl_xor_sync(0xffffffffu, mx0, 2));
    mx1 = fmaxf(mx1, __shfl_xor_sync(0xffffffffu, mx1, 1));
    mx1 = fmaxf(mx1, __shfl_xor_sync(0xffffffffu, mx1, 2));
    float s0 = 0.f, s1 = 0.f;
    #pragma unroll
    for (int nb = 0; nb < 8; nb++) {
        S[nb][0] = __expf(S[nb][0] - mx0); s0 += S[nb][0];
        S[nb][1] = __expf(S[nb][1] - mx0); s0 += S[nb][1];
        S[nb][2] = __expf(S[nb][2] - mx1); s1 += S[nb][2];
        S[nb][3] = __expf(S[nb][3] - mx1); s1 += S[nb][3];
    }
    s0 += __shfl_xor_sync(0xffffffffu, s0, 1);
    s0 += __shfl_xor_sync(0xffffffffu, s0, 2);
    s1 += __shfl_xor_sync(0xffffffffu, s1, 1);
    s1 += __shfl_xor_sync(0xffffffffu, s1, 2);
    float pinv0 = 1.f / s0, pinv1 = 1.f / s1;
    #pragma unroll
    for (int nb = 0; nb < 8; nb++) {
        S[nb][0] *= pinv0; S[nb][1] *= pinv0;
        S[nb][2] *= pinv1; S[nb][3] *= pinv1;
    }

    float O[3][4];
    #pragma unroll
    for (int nb3 = 0; nb3 < 3; nb3++)
        #pragma unroll
        for (int j = 0; j < 4; j++) O[nb3][j] = 0.f;

    #pragma unroll
    for (int kt = 0; kt < 4; kt++) {
        uint32_t a[4];
        a[0] = pack_h2(S[2 * kt][0],     S[2 * kt][1]);
        a[1] = pack_h2(S[2 * kt][2],     S[2 * kt][3]);
        a[2] = pack_h2(S[2 * kt + 1][0], S[2 * kt + 1][1]);
        a[3] = pack_h2(S[2 * kt + 1][2], S[2 * kt + 1][3]);
        uint32_t b[4];
        ldmx4(b, vb + (uint32_t)((((lane & 7) + ((lane >> 4) & 1) * 8) * 72
                                   + kt * 16 + ((lane >> 3) & 1) * 8) * 2));
        mma_f16(O[0], a, &b[0]);
        mma_f16(O[1], a, &b[2]);
        uint32_t b2[2];
        ldmx2(b2, vb + (uint32_t)(((16 + (lane & 7)) * 72
                                    + kt * 16 + (((lane & 15) >> 3) & 1) * 8) * 2));
        mma_f16(O[2], a, b2);
    }

    #pragma unroll
    for (int nb3 = 0; nb3 < 3; nb3++) {
        int d = nb3 * 8 + qc;
        os_[d * 72 + r0]       = __float2half(O[nb3][0]);
        os_[(d + 1) * 72 + r0] = __float2half(O[nb3][1]);
        os_[d * 72 + r1]       = __float2half(O[nb3][2]);
        os_[(d + 1) * 72 + r1] = __float2half(O[nb3][3]);
    }
    __syncthreads();

    __half* ga = g_atth + ((size_t)(bz * NWIN + win) * CDIM + h * HD) * 64;
    #pragma unroll
    for (int pass = 0; pass < 2; pass++) {
        int idx = tid + pass * 128;
        if (idx < 192) {
            int d = idx >> 3, tg = idx & 7;
            *(uint4*)(ga + d * 64 + tg * 8) = *(uint4*)&os_[d * 72 + tg * 8];
        }
    }
}

// ---------------- launch ----------------
extern "C" void kernel_launch(void* const* d_in, const int* in_sizes, int n_in,
                              void* d_out, int out_size)
{
    const float* x        = (const float*)d_in[0];
    const float* qkv_w    = (const float*)d_in[2];
    const float* q_bias   = (const float*)d_in[3];
    const float* v_bias   = (const float*)d_in[4];
    const float* lscale   = (const float*)d_in[5];
    const float* cpb_w1   = (const float*)d_in[6];
    const float* cpb_b1   = (const float*)d_in[7];
    const float* cpb_w2   = (const float*)d_in[8];
    const float* proj_w   = (const float*)d_in[9];
    const float* proj_b   = (const float*)d_in[10];
    float* out = (float*)d_out;

    __half *qkv_buf, *att_buf;
    float *bq, *bp;
    unsigned *wqf, *wpf;
    cudaGetSymbolAddress((void**)&qkv_buf, g_qkvh);
    cudaGetSymbolAddress((void**)&att_buf, g_atth);
    cudaGetSymbolAddress((void**)&wqf, g_wqf);
    cudaGetSymbolAddress((void**)&wpf, g_wpf);
    cudaGetSymbolAddress((void**)&bq, g_bq);
    cudaGetSymbolAddress((void**)&bp, g_bp);

    cudaFuncSetAttribute(gemm9<0>, cudaFuncAttributeMaxDynamicSharedMemorySize, SMEM_G);
    cudaFuncSetAttribute(gemm9<1>, cudaFuncAttributeMaxDynamicSharedMemorySize, SMEM_G);

    bias_kernel<<<1, 256>>>(cpb_w1, cpb_b1, cpb_w2);
    prep_kernel<<<128, 256>>>(qkv_w, q_bias, v_bias, proj_w, proj_b);

    // QKV: 5 m-tiles x 64 CTA-columns (8 n-tiles each) x 4 batch
    gemm9<0><<<dim3(MQ / 128, (HW / 128) / TILES_PER_CTA, NB), 256, SMEM_G>>>(
        wqf, bq, x, nullptr, qkv_buf, 576);

    // windowed cosine attention on window-native fp16
    attn4<<<dim3(NWIN, NH, NB), 128>>>(lscale);

    // proj + bias + residual -> fp32 output
    gemm9<1><<<dim3(MP / 128, (HW / 128) / TILES_PER_CTA, NB), 256, SMEM_G>>>(
        wpf, bp, att_buf, x, out, 192);
}

// round 15
// speedup vs baseline: 1.3513x; 1.0876x over previous
#include <cuda_runtime.h>
#include <cuda_fp16.h>
#include <math.h>
#include <cstdint>

#define NH   8
#define HD   24
#define CDIM 192
#define HW   65536   // 256*256
#define NB   4
#define KDIM 192
#define MQ   640     // qkv rows padded to 5*128 (576 valid)
#define MP   256
#define NWIN 1024    // 32x32 windows

#define BPADH  136
#define APM 12288
// gemm7 smem (bytes): A frags @0 : 49152 ; B fp16 tile @49152 : 192*136*2 = 52224
#define SB_TILE 49152
#define SMEM_G  101376

// ---------------- device scratch (fp16 window-native intermediates) ----------------
__device__ __half   g_qkvh[(size_t)NB * NWIN * 576 * 64];   // (B, win, ch, tok)
__device__ __half   g_atth[(size_t)NB * NWIN * CDIM * 64];  // (B, win, ch, tok)
__device__ float    g_bias[NH * 64 * 64];
__device__ unsigned g_wqf[5 * APM];
__device__ unsigned g_wpf[2 * APM];
__device__ float    g_bq[MQ];
__device__ float    g_bp[MP];

// ---------------- helpers ----------------
__device__ __forceinline__ uint32_t smem_u32(const void* p) {
    uint32_t a;
    asm("{ .reg .u64 t; cvta.to.shared.u64 t, %1; cvt.u32.u64 %0, t; }" : "=r"(a) : "l"(p));
    return a;
}
__device__ __forceinline__ void cpa16(uint32_t dst, const void* src) {
    asm volatile("cp.async.cg.shared.global [%0], [%1], 16;" :: "r"(dst), "l"(src));
}
__device__ __forceinline__ void lds128(uint32_t* r, uint32_t a) {
    asm volatile("ld.shared.v4.b32 {%0,%1,%2,%3}, [%4];"
                 : "=r"(r[0]), "=r"(r[1]), "=r"(r[2]), "=r"(r[3]) : "r"(a));
}
__device__ __forceinline__ void ldmx4(uint32_t* r, uint32_t a) {
    asm volatile("ldmatrix.sync.aligned.m8n8.x4.shared.b16 {%0,%1,%2,%3}, [%4];"
                 : "=r"(r[0]), "=r"(r[1]), "=r"(r[2]), "=r"(r[3]) : "r"(a));
}
__device__ __forceinline__ void ldmx4t(uint32_t* r, uint32_t a) {
    asm volatile("ldmatrix.sync.aligned.m8n8.x4.trans.shared.b16 {%0,%1,%2,%3}, [%4];"
                 : "=r"(r[0]), "=r"(r[1]), "=r"(r[2]), "=r"(r[3]) : "r"(a));
}
__device__ __forceinline__ void ldmx2(uint32_t* r, uint32_t a) {
    asm volatile("ldmatrix.sync.aligned.m8n8.x2.shared.b16 {%0,%1}, [%2];"
                 : "=r"(r[0]), "=r"(r[1]) : "r"(a));
}
__device__ __forceinline__ void mma_f16(float* c, const uint32_t* a, const uint32_t* b) {
    asm volatile("mma.sync.aligned.m16n8k16.row.col.f32.f16.f16.f32 "
                 "{%0,%1,%2,%3}, {%4,%5,%6,%7}, {%8,%9}, {%0,%1,%2,%3};"
                 : "+f"(c[0]), "+f"(c[1]), "+f"(c[2]), "+f"(c[3])
                 : "r"(a[0]), "r"(a[1]), "r"(a[2]), "r"(a[3]), "r"(b[0]), "r"(b[1]));
}
__device__ __forceinline__ uint32_t pack_h2(float lo, float hi) {
    __half2 h = __floats2half2_rn(lo, hi);
    return *(uint32_t*)&h;
}

// ---------------- kernel 1: CPB bias table ----------------
__global__ void bias_kernel(const float* __restrict__ w1, const float* __restrict__ b1,
                            const float* __restrict__ w2)
{
    __shared__ float table[225][NH];
    int tid = threadIdx.x;

    if (tid < 225) {
        int a = tid / 15, b = tid % 15;
        const float inv_l8 = 1.0f / log2f(8.0f);
        float ca = (float)(a - 7) / 7.0f * 8.0f;
        float cb = (float)(b - 7) / 7.0f * 8.0f;
        float r0 = (ca == 0.f) ? 0.f : copysignf(log2f(fabsf(ca) + 1.0f) * inv_l8, ca);
        float r1 = (cb == 0.f) ? 0.f : copysignf(log2f(fabsf(cb) + 1.0f) * inv_l8, cb);
        float acc[NH];
        #pragma unroll
        for (int h = 0; h < NH; h++) acc[h] = 0.f;
        for (int j = 0; j < 512; j++) {
            float hv = fmaf(r0, w1[j], fmaf(r1, w1[512 + j], b1[j]));
            hv = fmaxf(hv, 0.f);
            #pragma unroll
            for (int h = 0; h < NH; h++) acc[h] = fmaf(hv, w2[j * NH + h], acc[h]);
        }
        #pragma unroll
        for (int h = 0; h < NH; h++) table[tid][h] = acc[h];
    }
    __syncthreads();

    for (int idx = tid; idx < NH * 64 * 64; idx += blockDim.x) {
        int h  = idx / (64 * 64);
        int nm = idx % (64 * 64);
        int n = nm / 64, m = nm % 64;
        int di = (n >> 3) - (m >> 3) + 7;
        int dj = (n & 7) - (m & 7) + 7;
        float t = table[di * 15 + dj][h];
        g_bias[idx] = 16.f / (1.f + expf(-t));
    }
}

// ---------------- kernel 1b: pack weights into fp16 m16n8k16 fragment layout ----------------
__global__ void prep_kernel(const float* __restrict__ qkv_w, const float* __restrict__ qb,
                            const float* __restrict__ vb,
                            const float* __restrict__ proj_w, const float* __restrict__ pb)
{
    int i = blockIdx.x * blockDim.x + threadIdx.x;
    int stride = gridDim.x * blockDim.x;

    for (int idx = i; idx < 5 * APM; idx += stride) {
        int mt  = idx / APM;
        int r   = idx % APM;
        int kst = r / 2048;
        int r2  = r % 2048;
        int slot = r2 & 3, lane = (r2 >> 2) & 31, mf = (r2 >> 7) & 7, ks = (r2 >> 10) & 1;
        int m = mt * 128 + mf * 16 + (lane >> 2) + (slot & 1) * 8;
        int k = kst * 32 + ks * 16 + (lane & 3) * 2 + ((slot >> 1) & 1) * 8;
        float v0 = (m < 576) ? qkv_w[m * KDIM + k]     : 0.f;
        float v1 = (m < 576) ? qkv_w[m * KDIM + k + 1] : 0.f;
        g_wqf[idx] = pack_h2(v0, v1);
    }
    for (int idx = i; idx < 2 * APM; idx += stride) {
        int mt  = idx / APM;
        int r   = idx % APM;
        int kst = r / 2048;
        int r2  = r % 2048;
        int slot = r2 & 3, lane = (r2 >> 2) & 31, mf = (r2 >> 7) & 7, ks = (r2 >> 10) & 1;
        int m = mt * 128 + mf * 16 + (lane >> 2) + (slot & 1) * 8;
        int k = kst * 32 + ks * 16 + (lane & 3) * 2 + ((slot >> 1) & 1) * 8;
        float v0 = (m < 192) ? proj_w[m * KDIM + k]     : 0.f;
        float v1 = (m < 192) ? proj_w[m * KDIM + k + 1] : 0.f;
        g_wpf[idx] = pack_h2(v0, v1);
    }
    if (i < MQ) {
        float v = 0.f;
        if (i < 192)                  v = qb[i];
        else if (i >= 384 && i < 576) v = vb[i - 384];
        g_bq[i] = v;
    }
    if (i < MP) g_bp[i] = (i < 192) ? pb[i] : 0.f;
}

// ---------------- kernel 2/4: single-shot K fp16 mma GEMM, 2 CTA/SM (R11 proven) ----------------
template<int MODE>
__global__ void __launch_bounds__(256, 2) gemm7(
    const unsigned* __restrict__ Af,
    const float* __restrict__ bias,
    const void* __restrict__ Bsrc,
    const float* __restrict__ resid,
    void* __restrict__ outp,
    int Mvalid)
{
    extern __shared__ char sm[];
    const int tid = threadIdx.x;
    const int wid = tid >> 5, lane = tid & 31;
    const int wm = wid >> 1, wn = wid & 1;
    const int bz = blockIdx.z;
    const int m0 = blockIdx.x * 128;
    const int n0 = blockIdx.y * 128;
    const uint32_t sb = smem_u32(sm);

    const int py = n0 >> 8;

    {
        const char* Ag = (const char*)(Af + (size_t)blockIdx.x * APM);
        #pragma unroll
        for (int i = 0; i < 12; i++)
            cpa16(sb + (uint32_t)((i * 256 + tid) * 16), Ag + (i * 256 + tid) * 16);
        if (MODE == 1) {
            const __half* Bh = (const __half*)Bsrc;
            #pragma unroll
            for (int i = 0; i < 12; i++) {
                int c = tid + i * 256;
                int row = c >> 4, g = c & 15;
                int px = (n0 & 255) + g * 8;
                int winb = ((py >> 3) << 5) + (px >> 3);
                int tok0 = (py & 7) * 8;
                cpa16(sb + SB_TILE + (uint32_t)(row * BPADH + g * 8) * 2,
                      Bh + ((size_t)(bz * NWIN + winb) * CDIM + row) * 64 + tok0);
            }
        }
        asm volatile("cp.async.commit_group;");
    }

    if (MODE == 0) {
        const float* Xb = (const float*)Bsrc + (size_t)bz * KDIM * HW + n0;
        #pragma unroll
        for (int i = 0; i < 12; i++) {
            int c = tid + i * 256;
            int row = c >> 4, col8 = (c & 15) * 8;
            const float* src = Xb + (size_t)row * HW + col8;
            float4 p0 = *(const float4*)src;
            float4 p1 = *(const float4*)(src + 4);
            uint4 t;
            t.x = pack_h2(p0.x, p0.y); t.y = pack_h2(p0.z, p0.w);
            t.z = pack_h2(p1.x, p1.y); t.w = pack_h2(p1.z, p1.w);
            *(uint4*)(sm + SB_TILE + (row * BPADH + col8) * 2) = t;
        }
    }

    asm volatile("cp.async.wait_group 0;" ::: "memory");
    __syncthreads();

    const int lrow = (lane & 7) + ((lane >> 3) & 1) * 8;
    const int lcol = ((lane >> 4) & 1) * 8;
    const uint32_t Bb = sb + SB_TILE + (uint32_t)((lrow * BPADH + wn * 64 + lcol) * 2);

    float acc[2][8][4];
    #pragma unroll
    for (int mf = 0; mf < 2; mf++)
        #pragma unroll
        for (int nf = 0; nf < 8; nf++)
            #pragma unroll
            for (int j = 0; j < 4; j++) acc[mf][nf][j] = 0.f;

    #pragma unroll
    for (int kk = 0; kk < 12; kk++) {
        uint32_t a[2][4];
        const uint32_t Ab = sb + (kk >> 1) * 8192;
        lds128(a[0], Ab + (((kk & 1) * 8 + wm * 2 + 0) * 32 + lane) * 16);
        lds128(a[1], Ab + (((kk & 1) * 8 + wm * 2 + 1) * 32 + lane) * 16);
        uint32_t bm[4][4];
        #pragma unroll
        for (int nfp = 0; nfp < 4; nfp++)
            ldmx4t(bm[nfp], Bb + (uint32_t)((kk * 16 * BPADH + nfp * 16) * 2));
        #pragma unroll
        for (int mf = 0; mf < 2; mf++)
            #pragma unroll
            for (int nf = 0; nf < 8; nf++)
                mma_f16(acc[mf][nf], a[mf], &bm[nf >> 1][(nf & 1) * 2]);
    }

    const int gr = lane >> 2;
    const int qc = (lane & 3) * 2;

    if (MODE == 0) {
        __half* outW = (__half*)outp + (size_t)bz * NWIN * 576 * 64;
        #pragma unroll
        for (int mf = 0; mf < 2; mf++) {
            #pragma unroll
            for (int hh = 0; hh < 2; hh++) {
                int m = m0 + wm * 32 + mf * 16 + gr + hh * 8;
                if (m < Mvalid) {
                    float bv = bias[m];
                    #pragma unroll
                    for (int nf = 0; nf < 8; nf++) {
                        int px = (n0 & 255) + wn * 64 + nf * 8 + qc;
                        int win = ((py >> 3) << 5) + (px >> 3);
                        int tok = (py & 7) * 8 + (px & 7);
                        __half2 o = __floats2half2_rn(acc[mf][nf][hh * 2 + 0] + bv,
                                                      acc[mf][nf][hh * 2 + 1] + bv);
                        *(__half2*)&outW[((size_t)win * 576 + m) * 64 + tok] = o;
                    }
                }
            }
        }
    } else {
        float* outB = (float*)outp + (size_t)bz * CDIM * HW;
        const float* resB = resid + (size_t)bz * CDIM * HW;
        #pragma unroll
        for (int mf = 0; mf < 2; mf++) {
            #pragma unroll
            for (int hh = 0; hh < 2; hh++) {
                int m = m0 + wm * 32 + mf * 16 + gr + hh * 8;
                if (m < Mvalid) {
                    float bv = bias[m];
                    float* orow = outB + (size_t)m * HW + n0 + wn * 64 + qc;
                    const float* rrow = resB + (size_t)m * HW + n0 + wn * 64 + qc;
                    #pragma unroll
                    for (int nf = 0; nf < 8; nf++) {
                        float2 o;
                        o.x = acc[mf][nf][hh * 2 + 0] + bv;
                        o.y = acc[mf][nf][hh * 2 + 1] + bv;
                        float2 rv = *(const float2*)(rrow + nf * 8);
                        o.x += rv.x; o.y += rv.y;
                        *(float2*)(orow + nf * 8) = o;
                    }
                }
            }
        }
    }
}

// ---------------- kernel 3: tensor-core attention, HEAD-PAIR per block ----------------
// grid (NWIN, NH/2, NB), 256 threads / 8 warps; warps 0-3 -> head 0, 4-7 -> head 1.
__global__ void __launch_bounds__(256) attn5(const float* __restrict__ logit_scale)
{
    __shared__ __half qs_[2][32 * 72];
    __shared__ __half ks_[2][32 * 72];
    __shared__ __half vs_[2][24 * 72];
    __shared__ __half os_[2][24 * 72];
    __shared__ float qn[2][64], kn[2][64];

    const int tid  = threadIdx.x;
    const int lane = tid & 31;
    const int wr   = tid >> 5;        // 0..7
    const int g    = wr >> 2;         // head within pair
    const int wrl  = wr & 3;          // warp within head
    const int win  = blockIdx.x;
    const int hp   = blockIdx.y;
    const int bz   = blockIdx.z;
    const int h    = hp * 2 + g;

    const float LN100 = 4.6051701860f;

    // ---- contiguous loads: q/k/v = 48x64 half per array (2 heads) ----
    const __half* gbase = g_qkvh + (size_t)(bz * NWIN + win) * 576 * 64 + (size_t)(hp * 48) * 64;
    #pragma unroll
    for (int pass = 0; pass < 5; pass++) {
        int idx = tid + pass * 256;
        if (idx < 1152) {
            int arr = idx / 384, rem = idx % 384;
            int d48 = rem >> 3, tg = rem & 7;
            int g2 = d48 / 24, d = d48 - g2 * 24;
            uint4 val = *(const uint4*)(gbase + (size_t)arr * 192 * 64 + d48 * 64 + tg * 8);
            __half* dst = (arr == 0) ? qs_[g2] : (arr == 1) ? ks_[g2] : vs_[g2];
            *(uint4*)&dst[d * 72 + tg * 8] = val;
        }
    }
    {   // zero-pad q,k rows 24..31 for both heads
        int arr2 = tid >> 7, g2 = (tid >> 6) & 1, rr = (tid >> 3) & 7, tg = tid & 7;
        __half* dst = arr2 ? ks_[g2] : qs_[g2];
        *(uint4*)&dst[(24 + rr) * 72 + tg * 8] = make_uint4(0, 0, 0, 0);
    }
    __syncthreads();

    // ---- per-token inverse norms (256 = 2 heads x {q,k} x 64 tokens) ----
    {
        int t = tid & 63;
        int g2 = tid >> 7;
        int qk = (tid >> 6) & 1;
        const __half* col = qk ? ks_[g2] : qs_[g2];
        float ss = 0.f;
        #pragma unroll
        for (int d = 0; d < HD; d++) {
            float f = __half2float(col[d * 72 + t]);
            ss = fmaf(f, f, ss);
        }
        float inv = 1.f / fmaxf(sqrtf(ss), 1e-12f);
        if (qk) kn[g2][t] = inv;
        else {
            float sc = expf(fminf(logit_scale[hp * 2 + g2], LN100));
            qn[g2][t] = inv * sc;
        }
    }
    __syncthreads();

    const uint32_t qb = smem_u32(qs_[g]), kb = smem_u32(ks_[g]), vb = smem_u32(vs_[g]);
    const int gr = lane >> 2;
    const int qc = (lane & 3) * 2;
    const int r0 = wrl * 16 + gr, r1 = r0 + 8;

    // ---- S = Qraw Kraw^T (k over dims, padded to 32) ----
    float S[8][4];
    #pragma unroll
    for (int nb = 0; nb < 8; nb++)
        #pragma unroll
        for (int j = 0; j < 4; j++) S[nb][j] = 0.f;

    #pragma unroll
    for (int ks = 0; ks < 2; ks++) {
        uint32_t a[4];
        ldmx4t(a, qb + (uint32_t)(((ks * 16 + (lane & 7) + ((lane >> 4) & 1) * 8) * 72
                                   + wrl * 16 + ((lane >> 3) & 1) * 8) * 2));
        #pragma unroll
        for (int nbp = 0; nbp < 4; nbp++) {
            uint32_t b[4];
            ldmx4t(b, kb + (uint32_t)(((ks * 16 + (lane & 7) + ((lane >> 3) & 1) * 8) * 72
                                       + nbp * 16 + ((lane >> 4) & 1) * 8) * 2));
            mma_f16(S[nbp * 2],     a, &b[0]);
            mma_f16(S[nbp * 2 + 1], a, &b[2]);
        }
    }

    // ---- scale by qn*kn, add bias ----
    const float qn0 = qn[g][r0], qn1 = qn[g][r1];
    #pragma unroll
    for (int nb = 0; nb < 8; nb++) {
        int c0 = nb * 8 + qc;
        float k0v = kn[g][c0], k1v = kn[g][c0 + 1];
        float2 b0 = *(const float2*)&g_bias[(h * 64 + r0) * 64 + c0];
        float2 b1 = *(const float2*)&g_bias[(h * 64 + r1) * 64 + c0];
        S[nb][0] = S[nb][0] * qn0 * k0v + b0.x;
        S[nb][1] = S[nb][1] * qn0 * k1v + b0.y;
        S[nb][2] = S[nb][2] * qn1 * k0v + b1.x;
        S[nb][3] = S[nb][3] * qn1 * k1v + b1.y;
    }

    // ---- softmax (quad reduction, rows r0/r1) ----
    float mx0 = -1e30f, mx1 = -1e30f;
    #pragma unroll
    for (int nb = 0; nb < 8; nb++) {
        mx0 = fmaxf(mx0, fmaxf(S[nb][0], S[nb][1]));
        mx1 = fmaxf(mx1, fmaxf(S[nb][2], S[nb][3]));
    }
    mx0 = fmaxf(mx0, __shfl_xor_sync(0xffffffffu, mx0, 1));
    mx0 = fmaxf(mx0, __shfl_xor_sync(0xffffffffu, mx0, 2));
    mx1 = fmaxf(mx1, __shfl_xor_sync(0xffffffffu, mx1, 1));
    mx1 = fmaxf(mx1, __shfl_xor_sync(0xffffffffu, mx1, 2));
    float s0 = 0.f, s1 = 0.f;
    #pragma unroll
    for (int nb = 0; nb < 8; nb++) {
        S[nb][0] = __expf(S[nb][0] - mx0); s0 += S[nb][0];
        S[nb][1] = __expf(S[nb][1] - mx0); s0 += S[nb][1];
        S[nb][2] = __expf(S[nb][2] - mx1); s1 += S[nb][2];
        S[nb][3] = __expf(S[nb][3] - mx1); s1 += S[nb][3];
    }
    s0 += __shfl_xor_sync(0xffffffffu, s0, 1);
    s0 += __shfl_xor_sync(0xffffffffu, s0, 2);
    s1 += __shfl_xor_sync(0xffffffffu, s1, 1);
    s1 += __shfl_xor_sync(0xffffffffu, s1, 2);
    float pinv0 = 1.f / s0, pinv1 = 1.f / s1;
    #pragma unroll
    for (int nb = 0; nb < 8; nb++) {
        S[nb][0] *= pinv0; S[nb][1] *= pinv0;
        S[nb][2] *= pinv1; S[nb][3] *= pinv1;
    }

    // ---- O = P @ V ----
    float O[3][4];
    #pragma unroll
    for (int nb3 = 0; nb3 < 3; nb3++)
        #pragma unroll
        for (int j = 0; j < 4; j++) O[nb3][j] = 0.f;

    #pragma unroll
    for (int kt = 0; kt < 4; kt++) {
        uint32_t a[4];
        a[0] = pack_h2(S[2 * kt][0],     S[2 * kt][1]);
        a[1] = pack_h2(S[2 * kt][2],     S[2 * kt][3]);
        a[2] = pack_h2(S[2 * kt + 1][0], S[2 * kt + 1][1]);
        a[3] = pack_h2(S[2 * kt + 1][2], S[2 * kt + 1][3]);
        uint32_t b[4];
        ldmx4(b, vb + (uint32_t)((((lane & 7) + ((lane >> 4) & 1) * 8) * 72
                                   + kt * 16 + ((lane >> 3) & 1) * 8) * 2));
        mma_f16(O[0], a, &b[0]);
        mma_f16(O[1], a, &b[2]);
        uint32_t b2[2];
        ldmx2(b2, vb + (uint32_t)(((16 + (lane & 7)) * 72
                                    + kt * 16 + (((lane & 15) >> 3) & 1) * 8) * 2));
        mma_f16(O[2], a, b2);
    }

    // ---- O frags -> smem [d][t] -> contiguous global write ----
    #pragma unroll
    for (int nb3 = 0; nb3 < 3; nb3++) {
        int d = nb3 * 8 + qc;
        os_[g][d * 72 + r0]       = __float2half(O[nb3][0]);
        os_[g][(d + 1) * 72 + r0] = __float2half(O[nb3][1]);
        os_[g][d * 72 + r1]       = __float2half(O[nb3][2]);
        os_[g][(d + 1) * 72 + r1] = __float2half(O[nb3][3]);
    }
    __syncthreads();

    __half* ga = g_atth + ((size_t)(bz * NWIN + win) * CDIM + hp * 48) * 64;
    #pragma unroll
    for (int pass = 0; pass < 2; pass++) {
        int idx = tid + pass * 256;
        if (idx < 384) {
            int g2 = idx / 192, rem = idx % 192;
            int d = rem >> 3, tg = rem & 7;
            *(uint4*)(ga + (g2 * 24 + d) * 64 + tg * 8) = *(uint4*)&os_[g2][d * 72 + tg * 8];
        }
    }
}

// ---------------- launch ----------------
extern "C" void kernel_launch(void* const* d_in, const int* in_sizes, int n_in,
                              void* d_out, int out_size)
{
    const float* x        = (const float*)d_in[0];
    const float* qkv_w    = (const float*)d_in[2];
    const float* q_bias   = (const float*)d_in[3];
    const float* v_bias   = (const float*)d_in[4];
    const float* lscale   = (const float*)d_in[5];
    const float* cpb_w1   = (const float*)d_in[6];
    const float* cpb_b1   = (const float*)d_in[7];
    const float* cpb_w2   = (const float*)d_in[8];
    const float* proj_w   = (const float*)d_in[9];
    const float* proj_b   = (const float*)d_in[10];
    float* out = (float*)d_out;

    __half *qkv_buf, *att_buf;
    float *bq, *bp;
    unsigned *wqf, *wpf;
    cudaGetSymbolAddress((void**)&qkv_buf, g_qkvh);
    cudaGetSymbolAddress((void**)&att_buf, g_atth);
    cudaGetSymbolAddress((void**)&wqf, g_wqf);
    cudaGetSymbolAddress((void**)&wpf, g_wpf);
    cudaGetSymbolAddress((void**)&bq, g_bq);
    cudaGetSymbolAddress((void**)&bp, g_bp);

    cudaFuncSetAttribute(gemm7<0>, cudaFuncAttributeMaxDynamicSharedMemorySize, SMEM_G);
    cudaFuncSetAttribute(gemm7<1>, cudaFuncAttributeMaxDynamicSharedMemorySize, SMEM_G);

    bias_kernel<<<1, 256>>>(cpb_w1, cpb_b1, cpb_w2);
    prep_kernel<<<128, 256>>>(qkv_w, q_bias, v_bias, proj_w, proj_b);

    // QKV: fp16 window-layout output
    gemm7<0><<<dim3(MQ / 128, HW / 128, NB), 256, SMEM_G>>>(
        wqf, bq, x, nullptr, qkv_buf, 576);

    // windowed cosine attention: head-pair per block
    attn5<<<dim3(NWIN, NH / 2, NB), 256>>>(lscale);

    // proj + bias + residual -> fp32 output
    gemm7<1><<<dim3(MP / 128, HW / 128, NB), 256, SMEM_G>>>(
        wpf, bp, att_buf, x, out, 192);
}

// round 16
// speedup vs baseline: 1.3528x; 1.0011x over previous
#include <cuda_runtime.h>
#include <cuda_fp16.h>
#include <math.h>
#include <cstdint>

#define NH   8
#define HD   24
#define CDIM 192
#define HW   65536   // 256*256
#define NB   4
#define KDIM 192
#define MQ   640     // qkv rows padded to 5*128 (576 valid)
#define MP   256
#define NWIN 1024    // 32x32 windows

#define BPADH  136
#define APM 12288
// gemm7 smem (bytes): A frags @0 : 49152 ; B fp16 tile @49152 : 192*136*2 = 52224
#define SB_TILE 49152
#define SMEM_G  101376

// ---------------- device scratch (fp16 window-native intermediates) ----------------
__device__ __half   g_qkvh[(size_t)NB * NWIN * 576 * 64];   // (B, win, ch, tok)
__device__ __half   g_atth[(size_t)NB * NWIN * CDIM * 64];  // (B, win, ch, tok)
__device__ float    g_bias[NH * 64 * 64];
__device__ unsigned g_wqf[5 * APM];
__device__ unsigned g_wpf[2 * APM];
__device__ float    g_bq[MQ];
__device__ float    g_bp[MP];

// ---------------- helpers ----------------
__device__ __forceinline__ uint32_t smem_u32(const void* p) {
    uint32_t a;
    asm("{ .reg .u64 t; cvta.to.shared.u64 t, %1; cvt.u32.u64 %0, t; }" : "=r"(a) : "l"(p));
    return a;
}
__device__ __forceinline__ void cpa16(uint32_t dst, const void* src) {
    asm volatile("cp.async.cg.shared.global [%0], [%1], 16;" :: "r"(dst), "l"(src));
}
__device__ __forceinline__ void lds128(uint32_t* r, uint32_t a) {
    asm volatile("ld.shared.v4.b32 {%0,%1,%2,%3}, [%4];"
                 : "=r"(r[0]), "=r"(r[1]), "=r"(r[2]), "=r"(r[3]) : "r"(a));
}
__device__ __forceinline__ void ldmx4(uint32_t* r, uint32_t a) {
    asm volatile("ldmatrix.sync.aligned.m8n8.x4.shared.b16 {%0,%1,%2,%3}, [%4];"
                 : "=r"(r[0]), "=r"(r[1]), "=r"(r[2]), "=r"(r[3]) : "r"(a));
}
__device__ __forceinline__ void ldmx4t(uint32_t* r, uint32_t a) {
    asm volatile("ldmatrix.sync.aligned.m8n8.x4.trans.shared.b16 {%0,%1,%2,%3}, [%4];"
                 : "=r"(r[0]), "=r"(r[1]), "=r"(r[2]), "=r"(r[3]) : "r"(a));
}
__device__ __forceinline__ void ldmx2(uint32_t* r, uint32_t a) {
    asm volatile("ldmatrix.sync.aligned.m8n8.x2.shared.b16 {%0,%1}, [%2];"
                 : "=r"(r[0]), "=r"(r[1]) : "r"(a));
}
__device__ __forceinline__ void mma_f16(float* c, const uint32_t* a, const uint32_t* b) {
    asm volatile("mma.sync.aligned.m16n8k16.row.col.f32.f16.f16.f32 "
                 "{%0,%1,%2,%3}, {%4,%5,%6,%7}, {%8,%9}, {%0,%1,%2,%3};"
                 : "+f"(c[0]), "+f"(c[1]), "+f"(c[2]), "+f"(c[3])
                 : "r"(a[0]), "r"(a[1]), "r"(a[2]), "r"(a[3]), "r"(b[0]), "r"(b[1]));
}
__device__ __forceinline__ uint32_t pack_h2(float lo, float hi) {
    __half2 h = __floats2half2_rn(lo, hi);
    return *(uint32_t*)&h;
}

// ---------------- kernel 1: fused prep (weights pack + biases) + CPB bias table ----------------
// blocks 1..128: weight packing slices. block 0: ALSO computes the CPB table.
__global__ void prep_kernel(const float* __restrict__ qkv_w, const float* __restrict__ qb,
                            const float* __restrict__ vb,
                            const float* __restrict__ proj_w, const float* __restrict__ pb,
                            const float* __restrict__ w1, const float* __restrict__ b1,
                            const float* __restrict__ w2)
{
    __shared__ float table[225][NH];
    int tid = threadIdx.x;
    int i = blockIdx.x * blockDim.x + tid;
    int stride = gridDim.x * blockDim.x;

    // ---- CPB table (block 0 only) ----
    if (blockIdx.x == 0) {
        if (tid < 225) {
            int a = tid / 15, b = tid % 15;
            const float inv_l8 = 1.0f / log2f(8.0f);
            float ca = (float)(a - 7) / 7.0f * 8.0f;
            float cb = (float)(b - 7) / 7.0f * 8.0f;
            float r0 = (ca == 0.f) ? 0.f : copysignf(log2f(fabsf(ca) + 1.0f) * inv_l8, ca);
            float r1 = (cb == 0.f) ? 0.f : copysignf(log2f(fabsf(cb) + 1.0f) * inv_l8, cb);
            float acc[NH];
            #pragma unroll
            for (int h = 0; h < NH; h++) acc[h] = 0.f;
            for (int j = 0; j < 512; j++) {
                float hv = fmaf(r0, w1[j], fmaf(r1, w1[512 + j], b1[j]));
                hv = fmaxf(hv, 0.f);
                #pragma unroll
                for (int h = 0; h < NH; h++) acc[h] = fmaf(hv, w2[j * NH + h], acc[h]);
            }
            #pragma unroll
            for (int h = 0; h < NH; h++) table[tid][h] = acc[h];
        }
        __syncthreads();
        for (int idx = tid; idx < NH * 64 * 64; idx += blockDim.x) {
            int h  = idx / (64 * 64);
            int nm = idx % (64 * 64);
            int n = nm / 64, m = nm % 64;
            int di = (n >> 3) - (m >> 3) + 7;
            int dj = (n & 7) - (m & 7) + 7;
            float t = table[di * 15 + dj][h];
            g_bias[idx] = 16.f / (1.f + expf(-t));
        }
    }

    // ---- weight packing (all blocks) ----
    for (int idx = i; idx < 5 * APM; idx += stride) {
        int mt  = idx / APM;
        int r   = idx % APM;
        int kst = r / 2048;
        int r2  = r % 2048;
        int slot = r2 & 3, lane = (r2 >> 2) & 31, mf = (r2 >> 7) & 7, ks = (r2 >> 10) & 1;
        int m = mt * 128 + mf * 16 + (lane >> 2) + (slot & 1) * 8;
        int k = kst * 32 + ks * 16 + (lane & 3) * 2 + ((slot >> 1) & 1) * 8;
        float v0 = (m < 576) ? qkv_w[m * KDIM + k]     : 0.f;
        float v1 = (m < 576) ? qkv_w[m * KDIM + k + 1] : 0.f;
        g_wqf[idx] = pack_h2(v0, v1);
    }
    for (int idx = i; idx < 2 * APM; idx += stride) {
        int mt  = idx / APM;
        int r   = idx % APM;
        int kst = r / 2048;
        int r2  = r % 2048;
        int slot = r2 & 3, lane = (r2 >> 2) & 31, mf = (r2 >> 7) & 7, ks = (r2 >> 10) & 1;
        int m = mt * 128 + mf * 16 + (lane >> 2) + (slot & 1) * 8;
        int k = kst * 32 + ks * 16 + (lane & 3) * 2 + ((slot >> 1) & 1) * 8;
        float v0 = (m < 192) ? proj_w[m * KDIM + k]     : 0.f;
        float v1 = (m < 192) ? proj_w[m * KDIM + k + 1] : 0.f;
        g_wpf[idx] = pack_h2(v0, v1);
    }
    if (i < MQ) {
        float v = 0.f;
        if (i < 192)                  v = qb[i];
        else if (i >= 384 && i < 576) v = vb[i - 384];
        g_bq[i] = v;
    }
    if (i < MP) g_bp[i] = (i < 192) ? pb[i] : 0.f;
}

// ---------------- kernel 2/4: single-shot K fp16 mma GEMM, 2 CTA/SM (R11 proven) ----------------
template<int MODE>
__global__ void __launch_bounds__(256, 2) gemm7(
    const unsigned* __restrict__ Af,
    const float* __restrict__ bias,
    const void* __restrict__ Bsrc,
    const float* __restrict__ resid,
    void* __restrict__ outp,
    int Mvalid)
{
    extern __shared__ char sm[];
    const int tid = threadIdx.x;
    const int wid = tid >> 5, lane = tid & 31;
    const int wm = wid >> 1, wn = wid & 1;
    const int bz = blockIdx.z;
    const int m0 = blockIdx.x * 128;
    const int n0 = blockIdx.y * 128;
    const uint32_t sb = smem_u32(sm);

    const int py = n0 >> 8;

    {
        const char* Ag = (const char*)(Af + (size_t)blockIdx.x * APM);
        #pragma unroll
        for (int i = 0; i < 12; i++)
            cpa16(sb + (uint32_t)((i * 256 + tid) * 16), Ag + (i * 256 + tid) * 16);
        if (MODE == 1) {
            const __half* Bh = (const __half*)Bsrc;
            #pragma unroll
            for (int i = 0; i < 12; i++) {
                int c = tid + i * 256;
                int row = c >> 4, g = c & 15;
                int px = (n0 & 255) + g * 8;
                int winb = ((py >> 3) << 5) + (px >> 3);
                int tok0 = (py & 7) * 8;
                cpa16(sb + SB_TILE + (uint32_t)(row * BPADH + g * 8) * 2,
                      Bh + ((size_t)(bz * NWIN + winb) * CDIM + row) * 64 + tok0);
            }
        }
        asm volatile("cp.async.commit_group;");
    }

    if (MODE == 0) {
        const float* Xb = (const float*)Bsrc + (size_t)bz * KDIM * HW + n0;
        #pragma unroll
        for (int i = 0; i < 12; i++) {
            int c = tid + i * 256;
            int row = c >> 4, col8 = (c & 15) * 8;
            const float* src = Xb + (size_t)row * HW + col8;
            float4 p0 = *(const float4*)src;
            float4 p1 = *(const float4*)(src + 4);
            uint4 t;
            t.x = pack_h2(p0.x, p0.y); t.y = pack_h2(p0.z, p0.w);
            t.z = pack_h2(p1.x, p1.y); t.w = pack_h2(p1.z, p1.w);
            *(uint4*)(sm + SB_TILE + (row * BPADH + col8) * 2) = t;
        }
    }

    asm volatile("cp.async.wait_group 0;" ::: "memory");
    __syncthreads();

    const int lrow = (lane & 7) + ((lane >> 3) & 1) * 8;
    const int lcol = ((lane >> 4) & 1) * 8;
    const uint32_t Bb = sb + SB_TILE + (uint32_t)((lrow * BPADH + wn * 64 + lcol) * 2);

    float acc[2][8][4];
    #pragma unroll
    for (int mf = 0; mf < 2; mf++)
        #pragma unroll
        for (int nf = 0; nf < 8; nf++)
            #pragma unroll
            for (int j = 0; j < 4; j++) acc[mf][nf][j] = 0.f;

    #pragma unroll
    for (int kk = 0; kk < 12; kk++) {
        uint32_t a[2][4];
        const uint32_t Ab = sb + (kk >> 1) * 8192;
        lds128(a[0], Ab + (((kk & 1) * 8 + wm * 2 + 0) * 32 + lane) * 16);
        lds128(a[1], Ab + (((kk & 1) * 8 + wm * 2 + 1) * 32 + lane) * 16);
        uint32_t bm[4][4];
        #pragma unroll
        for (int nfp = 0; nfp < 4; nfp++)
            ldmx4t(bm[nfp], Bb + (uint32_t)((kk * 16 * BPADH + nfp * 16) * 2));
        #pragma unroll
        for (int mf = 0; mf < 2; mf++)
            #pragma unroll
            for (int nf = 0; nf < 8; nf++)
                mma_f16(acc[mf][nf], a[mf], &bm[nf >> 1][(nf & 1) * 2]);
    }

    const int gr = lane >> 2;
    const int qc = (lane & 3) * 2;

    if (MODE == 0) {
        __half* outW = (__half*)outp + (size_t)bz * NWIN * 576 * 64;
        #pragma unroll
        for (int mf = 0; mf < 2; mf++) {
            #pragma unroll
            for (int hh = 0; hh < 2; hh++) {
                int m = m0 + wm * 32 + mf * 16 + gr + hh * 8;
                if (m < Mvalid) {
                    float bv = bias[m];
                    #pragma unroll
                    for (int nf = 0; nf < 8; nf++) {
                        int px = (n0 & 255) + wn * 64 + nf * 8 + qc;
                        int win = ((py >> 3) << 5) + (px >> 3);
                        int tok = (py & 7) * 8 + (px & 7);
                        __half2 o = __floats2half2_rn(acc[mf][nf][hh * 2 + 0] + bv,
                                                      acc[mf][nf][hh * 2 + 1] + bv);
                        *(__half2*)&outW[((size_t)win * 576 + m) * 64 + tok] = o;
                    }
                }
            }
        }
    } else {
        float* outB = (float*)outp + (size_t)bz * CDIM * HW;
        const float* resB = resid + (size_t)bz * CDIM * HW;
        #pragma unroll
        for (int mf = 0; mf < 2; mf++) {
            #pragma unroll
            for (int hh = 0; hh < 2; hh++) {
                int m = m0 + wm * 32 + mf * 16 + gr + hh * 8;
                if (m < Mvalid) {
                    float bv = bias[m];
                    float* orow = outB + (size_t)m * HW + n0 + wn * 64 + qc;
                    const float* rrow = resB + (size_t)m * HW + n0 + wn * 64 + qc;
                    #pragma unroll
                    for (int nf = 0; nf < 8; nf++) {
                        float2 o;
                        o.x = acc[mf][nf][hh * 2 + 0] + bv;
                        o.y = acc[mf][nf][hh * 2 + 1] + bv;
                        float2 rv = *(const float2*)(rrow + nf * 8);
                        o.x += rv.x; o.y += rv.y;
                        *(float2*)(orow + nf * 8) = o;
                    }
                }
            }
        }
    }
}

// ---------------- kernel 3: tensor-core attention on window-native fp16 (R9/R11 proven) ----------------
__global__ void __launch_bounds__(128) attn4(const float* __restrict__ logit_scale)
{
    __shared__ __half qs_[32 * 72];
    __shared__ __half ks_[32 * 72];
    __shared__ __half vs_[24 * 72];
    __shared__ __half os_[24 * 72];
    __shared__ float qn[64], kn[64];

    const int tid  = threadIdx.x;
    const int lane = tid & 31;
    const int wr   = tid >> 5;
    const int win  = blockIdx.x;
    const int h    = blockIdx.y;
    const int bz   = blockIdx.z;

    const float LN100 = 4.6051701860f;
    const float scale_h = expf(fminf(logit_scale[h], LN100));

    const __half* gq = g_qkvh + ((size_t)(bz * NWIN + win) * 576 + h * HD) * 64;
    #pragma unroll
    for (int pass = 0; pass < 5; pass++) {
        int idx = tid + pass * 128;
        if (idx < 576) {
            int arr = idx / 192, rem = idx % 192;
            int d = rem >> 3, tg = rem & 7;
            uint4 val = *(const uint4*)(gq + (size_t)arr * 192 * 64 + d * 64 + tg * 8);
            __half* dst = (arr == 0) ? qs_ : (arr == 1) ? ks_ : vs_;
            *(uint4*)&dst[d * 72 + tg * 8] = val;
        }
    }
    {
        int arr2 = tid >> 6, rr = (tid >> 3) & 7, tg = tid & 7;
        __half* dst = arr2 ? ks_ : qs_;
        *(uint4*)&dst[(24 + rr) * 72 + tg * 8] = make_uint4(0, 0, 0, 0);
    }
    __syncthreads();

    {
        int t = tid & 63;
        const __half* col = (tid < 64) ? qs_ : ks_;
        float ss = 0.f;
        #pragma unroll
        for (int d = 0; d < HD; d++) {
            float f = __half2float(col[d * 72 + t]);
            ss = fmaf(f, f, ss);
        }
        float inv = 1.f / fmaxf(sqrtf(ss), 1e-12f);
        if (tid < 64) qn[t] = inv * scale_h; else kn[t] = inv;
    }
    __syncthreads();

    const uint32_t qb = smem_u32(qs_), kb = smem_u32(ks_), vb = smem_u32(vs_);
    const int gr = lane >> 2;
    const int qc = (lane & 3) * 2;
    const int r0 = wr * 16 + gr, r1 = r0 + 8;

    float S[8][4];
    #pragma unroll
    for (int nb = 0; nb < 8; nb++)
        #pragma unroll
        for (int j = 0; j < 4; j++) S[nb][j] = 0.f;

    #pragma unroll
    for (int ks = 0; ks < 2; ks++) {
        uint32_t a[4];
        ldmx4t(a, qb + (uint32_t)(((ks * 16 + (lane & 7) + ((lane >> 4) & 1) * 8) * 72
                                   + wr * 16 + ((lane >> 3) & 1) * 8) * 2));
        #pragma unroll
        for (int nbp = 0; nbp < 4; nbp++) {
            uint32_t b[4];
            ldmx4t(b, kb + (uint32_t)(((ks * 16 + (lane & 7) + ((lane >> 3) & 1) * 8) * 72
                                       + nbp * 16 + ((lane >> 4) & 1) * 8) * 2));
            mma_f16(S[nbp * 2],     a, &b[0]);
            mma_f16(S[nbp * 2 + 1], a, &b[2]);
        }
    }

    const float qn0 = qn[r0], qn1 = qn[r1];
    #pragma unroll
    for (int nb = 0; nb < 8; nb++) {
        int c0 = nb * 8 + qc;
        float k0v = kn[c0], k1v = kn[c0 + 1];
        float2 b0 = *(const float2*)&g_bias[(h * 64 + r0) * 64 + c0];
        float2 b1 = *(const float2*)&g_bias[(h * 64 + r1) * 64 + c0];
        S[nb][0] = S[nb][0] * qn0 * k0v + b0.x;
        S[nb][1] = S[nb][1] * qn0 * k1v + b0.y;
        S[nb][2] = S[nb][2] * qn1 * k0v + b1.x;
        S[nb][3] = S[nb][3] * qn1 * k1v + b1.y;
    }

    float mx0 = -1e30f, mx1 = -1e30f;
    #pragma unroll
    for (int nb = 0; nb < 8; nb++) {
        mx0 = fmaxf(mx0, fmaxf(S[nb][0], S[nb][1]));
        mx1 = fmaxf(mx1, fmaxf(S[nb][2], S[nb][3]));
    }
    mx0 = fmaxf(mx0, __shfl_xor_sync(0xffffffffu, mx0, 1));
    mx0 = fmaxf(mx0, __shfl_xor_sync(0xffffffffu, mx0, 2));
    mx1 = fmaxf(mx1, __shfl_xor_sync(0xffffffffu, mx1, 1));
    mx1 = fmaxf(mx1, __shfl_xor_sync(0xffffffffu, mx1, 2));
    float s0 = 0.f, s1 = 0.f;
    #pragma unroll
    for (int nb = 0; nb < 8; nb++) {
        S[nb][0] = __expf(S[nb][0] - mx0); s0 += S[nb][0];
        S[nb][1] = __expf(S[nb][1] - mx0); s0 += S[nb][1];
        S[nb][2] = __expf(S[nb][2] - mx1); s1 += S[nb][2];
        S[nb][3] = __expf(S[nb][3] - mx1); s1 += S[nb][3];
    }
    s0 += __shfl_xor_sync(0xffffffffu, s0, 1);
    s0 += __shfl_xor_sync(0xffffffffu, s0, 2);
    s1 += __shfl_xor_sync(0xffffffffu, s1, 1);
    s1 += __shfl_xor_sync(0xffffffffu, s1, 2);
    float pinv0 = 1.f / s0, pinv1 = 1.f / s1;
    #pragma unroll
    for (int nb = 0; nb < 8; nb++) {
        S[nb][0] *= pinv0; S[nb][1] *= pinv0;
        S[nb][2] *= pinv1; S[nb][3] *= pinv1;
    }

    float O[3][4];
    #pragma unroll
    for (int nb3 = 0; nb3 < 3; nb3++)
        #pragma unroll
        for (int j = 0; j < 4; j++) O[nb3][j] = 0.f;

    #pragma unroll
    for (int kt = 0; kt < 4; kt++) {
        uint32_t a[4];
        a[0] = pack_h2(S[2 * kt][0],     S[2 * kt][1]);
        a[1] = pack_h2(S[2 * kt][2],     S[2 * kt][3]);
        a[2] = pack_h2(S[2 * kt + 1][0], S[2 * kt + 1][1]);
        a[3] = pack_h2(S[2 * kt + 1][2], S[2 * kt + 1][3]);
        uint32_t b[4];
        ldmx4(b, vb + (uint32_t)((((lane & 7) + ((lane >> 4) & 1) * 8) * 72
                                   + kt * 16 + ((lane >> 3) & 1) * 8) * 2));
        mma_f16(O[0], a, &b[0]);
        mma_f16(O[1], a, &b[2]);
        uint32_t b2[2];
        ldmx2(b2, vb + (uint32_t)(((16 + (lane & 7)) * 72
                                    + kt * 16 + (((lane & 15) >> 3) & 1) * 8) * 2));
        mma_f16(O[2], a, b2);
    }

    #pragma unroll
    for (int nb3 = 0; nb3 < 3; nb3++) {
        int d = nb3 * 8 + qc;
        os_[d * 72 + r0]       = __float2half(O[nb3][0]);
        os_[(d + 1) * 72 + r0] = __float2half(O[nb3][1]);
        os_[d * 72 + r1]       = __float2half(O[nb3][2]);
        os_[(d + 1) * 72 + r1] = __float2half(O[nb3][3]);
    }
    __syncthreads();

    __half* ga = g_atth + ((size_t)(bz * NWIN + win) * CDIM + h * HD) * 64;
    #pragma unroll
    for (int pass = 0; pass < 2; pass++) {
        int idx = tid + pass * 128;
        if (idx < 192) {
            int d = idx >> 3, tg = idx & 7;
            *(uint4*)(ga + d * 64 + tg * 8) = *(uint4*)&os_[d * 72 + tg * 8];
        }
    }
}

// ---------------- launch ----------------
extern "C" void kernel_launch(void* const* d_in, const int* in_sizes, int n_in,
                              void* d_out, int out_size)
{
    const float* x        = (const float*)d_in[0];
    const float* qkv_w    = (const float*)d_in[2];
    const float* q_bias   = (const float*)d_in[3];
    const float* v_bias   = (const float*)d_in[4];
    const float* lscale   = (const float*)d_in[5];
    const float* cpb_w1   = (const float*)d_in[6];
    const float* cpb_b1   = (const float*)d_in[7];
    const float* cpb_w2   = (const float*)d_in[8];
    const float* proj_w   = (const float*)d_in[9];
    const float* proj_b   = (const float*)d_in[10];
    float* out = (float*)d_out;

    __half *qkv_buf, *att_buf;
    float *bq, *bp;
    unsigned *wqf, *wpf;
    cudaGetSymbolAddress((void**)&qkv_buf, g_qkvh);
    cudaGetSymbolAddress((void**)&att_buf, g_atth);
    cudaGetSymbolAddress((void**)&wqf, g_wqf);
    cudaGetSymbolAddress((void**)&wpf, g_wpf);
    cudaGetSymbolAddress((void**)&bq, g_bq);
    cudaGetSymbolAddress((void**)&bp, g_bp);

    cudaFuncSetAttribute(gemm7<0>, cudaFuncAttributeMaxDynamicSharedMemorySize, SMEM_G);
    cudaFuncSetAttribute(gemm7<1>, cudaFuncAttributeMaxDynamicSharedMemorySize, SMEM_G);

    // fused prep: weight packing + biases + CPB table
    prep_kernel<<<129, 256>>>(qkv_w, q_bias, v_bias, proj_w, proj_b,
                              cpb_w1, cpb_b1, cpb_w2);

    // QKV: fp16 window-layout output
    gemm7<0><<<dim3(MQ / 128, HW / 128, NB), 256, SMEM_G>>>(
        wqf, bq, x, nullptr, qkv_buf, 576);

    // windowed cosine attention on window-native fp16
    attn4<<<dim3(NWIN, NH, NB), 128>>>(lscale);

    // proj + bias + residual -> fp32 output
    gemm7<1><<<dim3(MP / 128, HW / 128, NB), 256, SMEM_G>>>(
        wpf, bp, att_buf, x, out, 192);
}